// round 9
// baseline (speedup 1.0000x reference)
#include <cuda_runtime.h>
#include <cuda_bf16.h>
#include <stdint.h>
#include <math.h>

// Problem constants
#define BTN 32      // B*T
#define LLEN 512    // L
#define DDIM 512    // D
#define NH 8        // H
#define ED 64       // KD == VD
#define MROWS (BTN * LLEN)   // 16384

// Scratch (device globals; allocation-free rule)
__device__ __align__(16) __nv_bfloat16 g_Xh[3 * MROWS * DDIM];
__device__ __align__(16) __nv_bfloat16 g_Xl[3 * MROWS * DDIM];
__device__ __align__(16) __nv_bfloat16 g_Wh[3 * DDIM * DDIM];
__device__ __align__(16) __nv_bfloat16 g_Wl[3 * DDIM * DDIM];
__device__ __align__(16) __nv_bfloat16 g_Qh[MROWS * DDIM];
__device__ __align__(16) __nv_bfloat16 g_Ql[MROWS * DDIM];
__device__ __align__(16) __nv_bfloat16 g_Kh[MROWS * DDIM];
__device__ __align__(16) __nv_bfloat16 g_Kl[MROWS * DDIM];
__device__ __align__(16) __nv_bfloat16 g_Vh[MROWS * DDIM];
__device__ __align__(16) __nv_bfloat16 g_Vl[MROWS * DDIM];
__device__ float g_A[BTN * NH * LLEN * ED];

// ---------------------------------------------------------------------------
// helpers
// ---------------------------------------------------------------------------
__device__ __forceinline__ uint32_t smem_u32(const void* p) {
    uint32_t a;
    asm("{ .reg .u64 t; cvta.to.shared.u64 t, %1; cvt.u32.u64 %0, t; }"
        : "=r"(a) : "l"(p));
    return a;
}

__device__ __forceinline__ void mma_bf16(float* d, const uint32_t* a, const uint32_t* b) {
    asm volatile(
        "mma.sync.aligned.m16n8k16.row.col.f32.bf16.bf16.f32 "
        "{%0,%1,%2,%3}, {%4,%5,%6,%7}, {%8,%9}, {%0,%1,%2,%3};"
        : "+f"(d[0]), "+f"(d[1]), "+f"(d[2]), "+f"(d[3])
        : "r"(a[0]), "r"(a[1]), "r"(a[2]), "r"(a[3]), "r"(b[0]), "r"(b[1]));
}

__device__ __forceinline__ void ldsm_x4(uint32_t* r, uint32_t addr) {
    asm volatile("ldmatrix.sync.aligned.m8n8.x4.shared.b16 {%0,%1,%2,%3}, [%4];"
                 : "=r"(r[0]), "=r"(r[1]), "=r"(r[2]), "=r"(r[3]) : "r"(addr));
}
__device__ __forceinline__ void ldsm_x4_t(uint32_t* r, uint32_t addr) {
    asm volatile("ldmatrix.sync.aligned.m8n8.x4.trans.shared.b16 {%0,%1,%2,%3}, [%4];"
                 : "=r"(r[0]), "=r"(r[1]), "=r"(r[2]), "=r"(r[3]) : "r"(addr));
}

#define CP16(dst, src) \
    asm volatile("cp.async.cg.shared.global [%0], [%1], 16;" :: "r"(dst), "l"(src))
#define CP_COMMIT() asm volatile("cp.async.commit_group;" ::: "memory")
#define CP_WAIT0()  asm volatile("cp.async.wait_group 0;" ::: "memory")
#define CP_WAIT2()  asm volatile("cp.async.wait_group 2;" ::: "memory")

__device__ __forceinline__ void split_bf16(float x, uint16_t& h, uint16_t& l) {
    __nv_bfloat16 hb = __float2bfloat16(x);
    float hf = __bfloat162float(hb);
    __nv_bfloat16 lb = __float2bfloat16(x - hf);
    h = __bfloat16_as_ushort(hb);
    l = __bfloat16_as_ushort(lb);
}

__device__ __forceinline__ void pack8(const float* xs, uint4& hi, uint4& lo) {
    uint16_t hs[8], ls[8];
#pragma unroll
    for (int j = 0; j < 8; j++) split_bf16(xs[j], hs[j], ls[j]);
    hi.x = (uint32_t)hs[0] | ((uint32_t)hs[1] << 16);
    hi.y = (uint32_t)hs[2] | ((uint32_t)hs[3] << 16);
    hi.z = (uint32_t)hs[4] | ((uint32_t)hs[5] << 16);
    hi.w = (uint32_t)hs[6] | ((uint32_t)hs[7] << 16);
    lo.x = (uint32_t)ls[0] | ((uint32_t)ls[1] << 16);
    lo.y = (uint32_t)ls[2] | ((uint32_t)ls[3] << 16);
    lo.z = (uint32_t)ls[4] | ((uint32_t)ls[5] << 16);
    lo.w = (uint32_t)ls[6] | ((uint32_t)ls[7] << 16);
}

__device__ __forceinline__ uint32_t pk2(float a, float b) {
    uint32_t r;
    asm("cvt.rn.bf16x2.f32 %0, %1, %2;" : "=r"(r) : "f"(b), "f"(a));
    return r;
}
__device__ __forceinline__ float rlo(float x) {
    return x - __bfloat162float(__float2bfloat16(x));
}

// ---------------------------------------------------------------------------
// prep kernels: fp32 -> bf16 hi/lo
// ---------------------------------------------------------------------------
__global__ void __launch_bounds__(256) prep_x(
    const float* __restrict__ q, const float* __restrict__ k, const float* __restrict__ v)
{
    const float* src = (blockIdx.z == 0) ? q : (blockIdx.z == 1) ? k : v;
    size_t base = (size_t)blockIdx.z * (MROWS * DDIM);
    size_t i = (size_t)blockIdx.x * 256 + threadIdx.x;
    const float4* s4 = (const float4*)src + i * 2;
    float4 a = s4[0], b = s4[1];
    float xs[8] = {a.x, a.y, a.z, a.w, b.x, b.y, b.z, b.w};
    uint4 hi, lo;
    pack8(xs, hi, lo);
    *(uint4*)&g_Xh[base + i * 8] = hi;
    *(uint4*)&g_Xl[base + i * 8] = lo;
}

__global__ void __launch_bounds__(256) prep_w(
    const float* __restrict__ Wq, const float* __restrict__ Wk, const float* __restrict__ Wv)
{
    const float* src = (blockIdx.z == 0) ? Wq : (blockIdx.z == 1) ? Wk : Wv;
    size_t base = (size_t)blockIdx.z * (DDIM * DDIM);
    size_t i = (size_t)blockIdx.x * 256 + threadIdx.x;
    const float4* s4 = (const float4*)src + i * 2;
    float4 a = s4[0], b = s4[1];
    float xs[8] = {a.x, a.y, a.z, a.w, b.x, b.y, b.z, b.w};
    uint4 hi, lo;
    pack8(xs, hi, lo);
    *(uint4*)&g_Wh[base + i * 8] = hi;
    *(uint4*)&g_Wl[base + i * 8] = lo;
}

// ---------------------------------------------------------------------------
// proj_pipe: 4-stage cp.async bf16 GEMM, CTA 128x128, BK=16, 2 CTAs/SM.
// ---------------------------------------------------------------------------
#define ST_AH 0
#define ST_AL 6144
#define ST_BH 12288
#define ST_BL 16640
#define ST_SZ 20992
#define NSTG 4
#define PROJ_SMEM (NSTG * ST_SZ)

__global__ void __launch_bounds__(256, 2) proj_pipe()
{
    extern __shared__ char smc[];
    const uint32_t sb = smem_u32(smc);

    const int tid  = threadIdx.x;
    const int wid  = tid >> 5;
    const int lane = tid & 31;
    const int wm   = wid & 3;
    const int wn   = wid >> 2;

    const int p  = blockIdx.z;
    const int m0 = blockIdx.y * 128;
    const int n0 = blockIdx.x * 128;

    const __nv_bfloat16* Xh_ = g_Xh + (size_t)p * (MROWS * DDIM);
    const __nv_bfloat16* Xl_ = g_Xl + (size_t)p * (MROWS * DDIM);
    const __nv_bfloat16* Wh_ = g_Wh + (size_t)p * (DDIM * DDIM);
    const __nv_bfloat16* Wl_ = g_Wl + (size_t)p * (DDIM * DDIM);
    __nv_bfloat16* Ch = (p == 0) ? g_Qh : (p == 1) ? g_Kh : g_Vh;
    __nv_bfloat16* Cl = (p == 0) ? g_Ql : (p == 1) ? g_Kl : g_Vl;

    const int ar = tid >> 1, ac = tid & 1;
    const int br = tid >> 4, bc = tid & 15;
    const size_t ga0 = (size_t)(m0 + ar) * 512 + ac * 8;
    const size_t gb0 = (size_t)br * 512 + n0 + bc * 8;
    const uint32_t da = ar * 48 + ac * 16;
    const uint32_t db = br * 272 + bc * 16;

    const uint32_t a_lane = (uint32_t)(((wm * 32 + (lane & 15)) * 24 + (lane >> 4) * 8) * 2);
    const uint32_t b_lane = (uint32_t)(((lane & 15) * 136 + wn * 64 + (lane >> 4) * 8) * 2);

    float acc[2][8][4];
#pragma unroll
    for (int i = 0; i < 2; i++)
#pragma unroll
        for (int j = 0; j < 8; j++)
#pragma unroll
            for (int q = 0; q < 4; q++) acc[i][j][q] = 0.f;

#pragma unroll
    for (int s = 0; s < 3; s++) {
        const uint32_t st = sb + s * ST_SZ;
        const size_t ka = (size_t)s * 16;
        CP16(st + ST_AH + da, Xh_ + ga0 + ka);
        CP16(st + ST_AL + da, Xl_ + ga0 + ka);
        CP16(st + ST_BH + db, Wh_ + gb0 + ka * 512);
        CP16(st + ST_BL + db, Wl_ + gb0 + ka * 512);
        CP_COMMIT();
    }

    for (int c = 0; c < 32; c++) {
        CP_WAIT2();
        __syncthreads();

        if (c + 3 < 32) {
            const uint32_t st = sb + ((c + 3) & 3) * ST_SZ;
            const size_t ka = (size_t)(c + 3) * 16;
            CP16(st + ST_AH + da, Xh_ + ga0 + ka);
            CP16(st + ST_AL + da, Xl_ + ga0 + ka);
            CP16(st + ST_BH + db, Wh_ + gb0 + ka * 512);
            CP16(st + ST_BL + db, Wl_ + gb0 + ka * 512);
        }
        CP_COMMIT();

        const uint32_t stc = sb + (c & 3) * ST_SZ;
        uint32_t ah[2][4], al[2][4];
#pragma unroll
        for (int mt = 0; mt < 2; mt++) {
            const uint32_t ao = stc + a_lane + mt * 768;
            ldsm_x4(ah[mt], ao + ST_AH);
            ldsm_x4(al[mt], ao + ST_AL);
        }
#pragma unroll
        for (int np = 0; np < 4; np++) {
            uint32_t bh[4], bl[4];
            const uint32_t bo = stc + b_lane + np * 32;
            ldsm_x4_t(bh, bo + ST_BH);
            ldsm_x4_t(bl, bo + ST_BL);
#pragma unroll
            for (int mt = 0; mt < 2; mt++) {
#pragma unroll
                for (int nt = 0; nt < 2; nt++) {
                    float* d = acc[mt][np * 2 + nt];
                    mma_bf16(d, ah[mt], bh + nt * 2);
                    mma_bf16(d, al[mt], bh + nt * 2);
                    mma_bf16(d, ah[mt], bl + nt * 2);
                }
            }
        }
    }

    const int g = lane >> 2;
    const int t = lane & 3;
#pragma unroll
    for (int mt = 0; mt < 2; mt++) {
#pragma unroll
        for (int np = 0; np < 4; np++) {
#pragma unroll
            for (int nt = 0; nt < 2; nt++) {
                const float* d = acc[mt][np * 2 + nt];
                int row = m0 + wm * 32 + mt * 16 + g;
                int col = n0 + wn * 64 + np * 16 + nt * 8 + t * 2;
                uint16_t h0, l0, h1, l1;
                split_bf16(d[0], h0, l0);
                split_bf16(d[1], h1, l1);
                *(uint32_t*)(Ch + (size_t)row * 512 + col) = (uint32_t)h0 | ((uint32_t)h1 << 16);
                *(uint32_t*)(Cl + (size_t)row * 512 + col) = (uint32_t)l0 | ((uint32_t)l1 << 16);
                split_bf16(d[2], h0, l0);
                split_bf16(d[3], h1, l1);
                *(uint32_t*)(Ch + (size_t)(row + 8) * 512 + col) = (uint32_t)h0 | ((uint32_t)h1 << 16);
                *(uint32_t*)(Cl + (size_t)(row + 8) * 512 + col) = (uint32_t)l0 | ((uint32_t)l1 << 16);
            }
        }
    }
}

// ---------------------------------------------------------------------------
// Flash attention WITHOUT online max (scores provably small; softmax is
// shift-invariant; exp2-domain transform).  1 CTA (128 thr) per (bth, l64).
// ---------------------------------------------------------------------------
#define AQH 0
#define AQL 9216
#define AST 18432
#define STG 36864
#define ATT_SMEM 92160

__global__ void __launch_bounds__(128, 2) attn_flash(
    const float* __restrict__ mask,
    const float* __restrict__ tau,
    const float* __restrict__ delta)
{
    extern __shared__ char smc[];
    const uint32_t sb = smem_u32(smc);

    const int tid  = threadIdx.x;
    const int wid  = tid >> 5;
    const int lane = tid & 31;
    const int wm   = wid;

    const int bth = blockIdx.x;
    const int bt  = bth >> 3;
    const int h   = bth & 7;
    const int l0  = blockIdx.y * 64;

    // fold scale (0.125) and log2(e) into tau/delta
    const float ts = tau[0] * 0.125f * 1.4426950408889634f;
    const float ds = delta[0] * 0.125f * 1.4426950408889634f;

    const size_t hb = (size_t)bt * 512 * 512 + h * 64;
    const __nv_bfloat16* Kh_ = g_Kh + hb;
    const __nv_bfloat16* Kl_ = g_Kl + hb;
    const __nv_bfloat16* Vh_ = g_Vh + hb;
    const __nv_bfloat16* Vl_ = g_Vl + hb;

    const int arow = lane & 15;
    const int acol = (lane >> 4) * 8;
    const int krow = (lane & 7) | ((lane & 16) >> 1);
    const int kcol = lane & 8;
    const int g    = lane >> 2;
    const int tc   = (lane & 3) * 2;

    {
#pragma unroll
        for (int i = 0; i < 4; i++) {
            int q = tid + i * 128;
            int row = q >> 3, c16 = q & 7;
            size_t gs = (size_t)row * 512 + c16 * 8;
            uint32_t dr = sb + AST + row * 144 + c16 * 16;
            CP16(dr +     0, Kh_ + gs);
            CP16(dr +  9216, Kl_ + gs);
            CP16(dr + 18432, Vh_ + gs);
            CP16(dr + 27648, Vl_ + gs);
        }
        CP_COMMIT();
    }

    {
        const __nv_bfloat16* Qh_ = g_Qh + hb + (size_t)l0 * 512;
        const __nv_bfloat16* Ql_ = g_Ql + hb + (size_t)l0 * 512;
#pragma unroll
        for (int i = 0; i < 8; i++) {
            int arr = i >> 2;
            int q = tid + (i & 3) * 128;
            int row = q >> 3, c16 = q & 7;
            size_t gs = (size_t)row * 512 + c16 * 8;
            const __nv_bfloat16* src = arr ? Ql_ : Qh_;
            *(uint4*)(smc + (arr ? AQL : AQH) + row * 144 + c16 * 16) =
                *(const uint4*)(src + gs);
        }
    }
    __syncthreads();

    uint32_t qfh[4][4], qfl[4][4];
#pragma unroll
    for (int kk = 0; kk < 4; kk++) {
        uint32_t qoff = (uint32_t)(((wm * 16 + arow) * 72 + acol + kk * 16) * 2);
        ldsm_x4(qfh[kk], sb + AQH + qoff);
        ldsm_x4(qfl[kk], sb + AQL + qoff);
    }

    float O[8][4];
#pragma unroll
    for (int j = 0; j < 8; j++)
#pragma unroll
        for (int q = 0; q < 4; q++) O[j][q] = 0.f;
    float l_g = 0.f, l_h = 0.f;

    const float* mrow0 = mask + (size_t)(l0 + wm * 16 + g) * 512;
    const float* mrow1 = mrow0 + 8 * 512;

    for (int sc = 0; sc < 8; sc++) {
        CP_WAIT0();
        __syncthreads();
        const uint32_t stoff = sb + AST + (sc & 1) * STG;

        if (sc < 7) {
            const int s_row0 = (sc + 1) * 64;
            const uint32_t nst = sb + AST + ((sc + 1) & 1) * STG;
#pragma unroll
            for (int i = 0; i < 4; i++) {
                int q = tid + i * 128;
                int row = q >> 3, c16 = q & 7;
                size_t gs = (size_t)(s_row0 + row) * 512 + c16 * 8;
                uint32_t dr = nst + row * 144 + c16 * 16;
                CP16(dr +     0, Kh_ + gs);
                CP16(dr +  9216, Kl_ + gs);
                CP16(dr + 18432, Vh_ + gs);
                CP16(dr + 27648, Vl_ + gs);
            }
            CP_COMMIT();
        }

        // ---- QK^T for this 64-col s-tile ----
        float s[8][4];
#pragma unroll
        for (int j = 0; j < 8; j++)
#pragma unroll
            for (int q = 0; q < 4; q++) s[j][q] = 0.f;

#pragma unroll
        for (int kk = 0; kk < 4; kk++) {
#pragma unroll
            for (int np = 0; np < 4; np++) {
                uint32_t bh[4], bl[4];
                uint32_t koff = (uint32_t)(((np * 16 + krow) * 72 + kcol + kk * 16) * 2);
                ldsm_x4(bh, stoff + 0 + koff);
                ldsm_x4(bl, stoff + 9216 + koff);
#pragma unroll
                for (int nt = 0; nt < 2; nt++) {
                    float* d = s[np * 2 + nt];
                    mma_bf16(d, qfh[kk], bh + nt * 2);
                    mma_bf16(d, qfl[kk], bh + nt * 2);
                    mma_bf16(d, qfh[kk], bl + nt * 2);
                }
            }
        }

        // ---- transform + mask + exp2 (no max subtraction) ----
        float sg = 0.f, sh = 0.f;
#pragma unroll
        for (int j = 0; j < 8; j++) {
            const int col = sc * 64 + j * 8 + tc;
            float2 mk0 = *(const float2*)&mrow0[col];
            float2 mk1 = *(const float2*)&mrow1[col];
            s[j][0] = exp2f((s[j][0] * ts + ds) * mk0.x);
            s[j][1] = exp2f((s[j][1] * ts + ds) * mk0.y);
            s[j][2] = exp2f((s[j][2] * ts + ds) * mk1.x);
            s[j][3] = exp2f((s[j][3] * ts + ds) * mk1.y);
            sg += s[j][0] + s[j][1];
            sh += s[j][2] + s[j][3];
        }
        l_g += sg;
        l_h += sh;

        // ---- P @ V ----
#pragma unroll
        for (int mkk = 0; mkk < 4; mkk++) {
            const float* p0 = s[2 * mkk];
            const float* p1 = s[2 * mkk + 1];
            uint32_t pah[4], pal[4];
            pah[0] = pk2(p0[0], p0[1]);
            pah[1] = pk2(p0[2], p0[3]);
            pah[2] = pk2(p1[0], p1[1]);
            pah[3] = pk2(p1[2], p1[3]);
            pal[0] = pk2(rlo(p0[0]), rlo(p0[1]));
            pal[1] = pk2(rlo(p0[2]), rlo(p0[3]));
            pal[2] = pk2(rlo(p1[0]), rlo(p1[1]));
            pal[3] = pk2(rlo(p1[2]), rlo(p1[3]));
#pragma unroll
            for (int vn = 0; vn < 4; vn++) {
                uint32_t vh[4], vl[4];
                uint32_t voff = (uint32_t)(((mkk * 16 + arow) * 72 + vn * 16 + acol) * 2);
                ldsm_x4_t(vh, stoff + 18432 + voff);
                ldsm_x4_t(vl, stoff + 27648 + voff);
#pragma unroll
                for (int nt = 0; nt < 2; nt++) {
                    float* d = O[vn * 2 + nt];
                    mma_bf16(d, pah, vh + nt * 2);
                    mma_bf16(d, pal, vh + nt * 2);
                    mma_bf16(d, pah, vl + nt * 2);
                }
            }
        }
    }

    // ---- finalize ----
    float lg = l_g;
    lg += __shfl_xor_sync(0xffffffffu, lg, 1);
    lg += __shfl_xor_sync(0xffffffffu, lg, 2);
    float lh = l_h;
    lh += __shfl_xor_sync(0xffffffffu, lh, 1);
    lh += __shfl_xor_sync(0xffffffffu, lh, 2);
    const float ig = 1.0f / lg;
    const float ih = 1.0f / lh;

    float* dst0 = g_A + ((size_t)bth * 512 + l0 + wm * 16 + g) * 64;
#pragma unroll
    for (int vn = 0; vn < 4; vn++) {
#pragma unroll
        for (int nt = 0; nt < 2; nt++) {
            const float* d = O[vn * 2 + nt];
            const int col = vn * 16 + nt * 8 + tc;
            *(float2*)(dst0 + col)          = make_float2(d[0] * ig, d[1] * ig);
            *(float2*)(dst0 + 8 * 64 + col) = make_float2(d[2] * ih, d[3] * ih);
        }
    }
}

// ---------------------------------------------------------------------------
// Head reduction
// ---------------------------------------------------------------------------
__global__ void __launch_bounds__(256) reduce_heads(
    const float* __restrict__ w_head, float* __restrict__ out)
{
    int idx = blockIdx.x * 256 + threadIdx.x;
    int bt   = idx >> 15;
    int rest = idx & 32767;
    float s = 0.f;
#pragma unroll
    for (int h = 0; h < 8; h++)
        s += w_head[h] * g_A[(((size_t)bt * 8 + h) << 15) + rest];
    out[idx] = s;
}

// ---------------------------------------------------------------------------
extern "C" void kernel_launch(void* const* d_in, const int* in_sizes, int n_in,
                              void* d_out, int out_size)
{
    const float* queries = (const float*)d_in[0];
    const float* keys    = (const float*)d_in[1];
    const float* values  = (const float*)d_in[2];
    const float* mask    = (const float*)d_in[3];
    const float* Wq      = (const float*)d_in[4];
    const float* Wk      = (const float*)d_in[5];
    const float* Wv      = (const float*)d_in[6];
    const float* w_head  = (const float*)d_in[7];
    const float* tau     = (const float*)d_in[8];
    const float* delta   = (const float*)d_in[9];
    float* out = (float*)d_out;
    (void)in_sizes; (void)n_in; (void)out_size;

    cudaFuncSetAttribute(proj_pipe,
                         cudaFuncAttributeMaxDynamicSharedMemorySize, PROJ_SMEM);
    cudaFuncSetAttribute(attn_flash,
                         cudaFuncAttributeMaxDynamicSharedMemorySize, ATT_SMEM);

    prep_x<<<dim3(4096, 1, 3), 256>>>(queries, keys, values);
    prep_w<<<dim3(128, 1, 3), 256>>>(Wq, Wk, Wv);

    proj_pipe<<<dim3(4, 128, 3), 256, PROJ_SMEM>>>();

    attn_flash<<<dim3(256, 8), 128, ATT_SMEM>>>(mask, tau, delta);

    reduce_heads<<<4096, 256>>>(w_head, out);
}

// round 10
// speedup vs baseline: 1.4250x; 1.4250x over previous
#include <cuda_runtime.h>
#include <cuda_bf16.h>
#include <stdint.h>
#include <math.h>

// Problem constants
#define BTN 32      // B*T
#define LLEN 512    // L
#define DDIM 512    // D
#define NH 8        // H
#define ED 64       // KD == VD
#define MROWS (BTN * LLEN)   // 16384

// Scratch (device globals; allocation-free rule)
__device__ __align__(16) __nv_bfloat16 g_Xh[3 * MROWS * DDIM];
__device__ __align__(16) __nv_bfloat16 g_Xl[3 * MROWS * DDIM];
__device__ __align__(16) __nv_bfloat16 g_Wh[3 * DDIM * DDIM];
__device__ __align__(16) __nv_bfloat16 g_Wl[3 * DDIM * DDIM];
__device__ __align__(16) __nv_bfloat16 g_Qh[MROWS * DDIM];
__device__ __align__(16) __nv_bfloat16 g_Ql[MROWS * DDIM];
__device__ __align__(16) __nv_bfloat16 g_Kh[MROWS * DDIM];
__device__ __align__(16) __nv_bfloat16 g_Kl[MROWS * DDIM];
__device__ __align__(16) __nv_bfloat16 g_Vh[MROWS * DDIM];
__device__ __align__(16) __nv_bfloat16 g_Vl[MROWS * DDIM];
__device__ float g_A[BTN * NH * LLEN * ED];

// ---------------------------------------------------------------------------
// helpers
// ---------------------------------------------------------------------------
__device__ __forceinline__ uint32_t smem_u32(const void* p) {
    uint32_t a;
    asm("{ .reg .u64 t; cvta.to.shared.u64 t, %1; cvt.u32.u64 %0, t; }"
        : "=r"(a) : "l"(p));
    return a;
}

__device__ __forceinline__ void mma_bf16(float* d, const uint32_t* a, const uint32_t* b) {
    asm volatile(
        "mma.sync.aligned.m16n8k16.row.col.f32.bf16.bf16.f32 "
        "{%0,%1,%2,%3}, {%4,%5,%6,%7}, {%8,%9}, {%0,%1,%2,%3};"
        : "+f"(d[0]), "+f"(d[1]), "+f"(d[2]), "+f"(d[3])
        : "r"(a[0]), "r"(a[1]), "r"(a[2]), "r"(a[3]), "r"(b[0]), "r"(b[1]));
}

__device__ __forceinline__ void ldsm_x4(uint32_t* r, uint32_t addr) {
    asm volatile("ldmatrix.sync.aligned.m8n8.x4.shared.b16 {%0,%1,%2,%3}, [%4];"
                 : "=r"(r[0]), "=r"(r[1]), "=r"(r[2]), "=r"(r[3]) : "r"(addr));
}
__device__ __forceinline__ void ldsm_x4_t(uint32_t* r, uint32_t addr) {
    asm volatile("ldmatrix.sync.aligned.m8n8.x4.trans.shared.b16 {%0,%1,%2,%3}, [%4];"
                 : "=r"(r[0]), "=r"(r[1]), "=r"(r[2]), "=r"(r[3]) : "r"(addr));
}

#define CP16(dst, src) \
    asm volatile("cp.async.cg.shared.global [%0], [%1], 16;" :: "r"(dst), "l"(src))
#define CP_COMMIT() asm volatile("cp.async.commit_group;" ::: "memory")
#define CP_WAIT0()  asm volatile("cp.async.wait_group 0;" ::: "memory")
#define CP_WAIT2()  asm volatile("cp.async.wait_group 2;" ::: "memory")

__device__ __forceinline__ void split_bf16(float x, uint16_t& h, uint16_t& l) {
    __nv_bfloat16 hb = __float2bfloat16(x);
    float hf = __bfloat162float(hb);
    __nv_bfloat16 lb = __float2bfloat16(x - hf);
    h = __bfloat16_as_ushort(hb);
    l = __bfloat16_as_ushort(lb);
}

__device__ __forceinline__ void pack8(const float* xs, uint4& hi, uint4& lo) {
    uint16_t hs[8], ls[8];
#pragma unroll
    for (int j = 0; j < 8; j++) split_bf16(xs[j], hs[j], ls[j]);
    hi.x = (uint32_t)hs[0] | ((uint32_t)hs[1] << 16);
    hi.y = (uint32_t)hs[2] | ((uint32_t)hs[3] << 16);
    hi.z = (uint32_t)hs[4] | ((uint32_t)hs[5] << 16);
    hi.w = (uint32_t)hs[6] | ((uint32_t)hs[7] << 16);
    lo.x = (uint32_t)ls[0] | ((uint32_t)ls[1] << 16);
    lo.y = (uint32_t)ls[2] | ((uint32_t)ls[3] << 16);
    lo.z = (uint32_t)ls[4] | ((uint32_t)ls[5] << 16);
    lo.w = (uint32_t)ls[6] | ((uint32_t)ls[7] << 16);
}

__device__ __forceinline__ uint32_t pk2(float a, float b) {
    uint32_t r;
    asm("cvt.rn.bf16x2.f32 %0, %1, %2;" : "=r"(r) : "f"(b), "f"(a));
    return r;
}
__device__ __forceinline__ float rlo(float x) {
    return x - __bfloat162float(__float2bfloat16(x));
}

// ---------------------------------------------------------------------------
// prep kernels: fp32 -> bf16 hi/lo
// ---------------------------------------------------------------------------
__global__ void __launch_bounds__(256) prep_x(
    const float* __restrict__ q, const float* __restrict__ k, const float* __restrict__ v)
{
    const float* src = (blockIdx.z == 0) ? q : (blockIdx.z == 1) ? k : v;
    size_t base = (size_t)blockIdx.z * (MROWS * DDIM);
    size_t i = (size_t)blockIdx.x * 256 + threadIdx.x;
    const float4* s4 = (const float4*)src + i * 2;
    float4 a = s4[0], b = s4[1];
    float xs[8] = {a.x, a.y, a.z, a.w, b.x, b.y, b.z, b.w};
    uint4 hi, lo;
    pack8(xs, hi, lo);
    *(uint4*)&g_Xh[base + i * 8] = hi;
    *(uint4*)&g_Xl[base + i * 8] = lo;
}

__global__ void __launch_bounds__(256) prep_w(
    const float* __restrict__ Wq, const float* __restrict__ Wk, const float* __restrict__ Wv)
{
    const float* src = (blockIdx.z == 0) ? Wq : (blockIdx.z == 1) ? Wk : Wv;
    size_t base = (size_t)blockIdx.z * (DDIM * DDIM);
    size_t i = (size_t)blockIdx.x * 256 + threadIdx.x;
    const float4* s4 = (const float4*)src + i * 2;
    float4 a = s4[0], b = s4[1];
    float xs[8] = {a.x, a.y, a.z, a.w, b.x, b.y, b.z, b.w};
    uint4 hi, lo;
    pack8(xs, hi, lo);
    *(uint4*)&g_Wh[base + i * 8] = hi;
    *(uint4*)&g_Wl[base + i * 8] = lo;
}

// ---------------------------------------------------------------------------
// proj_pipe: 4-stage cp.async bf16 GEMM, CTA 128x128, BK=16, 2 CTAs/SM.
// ---------------------------------------------------------------------------
#define ST_AH 0
#define ST_AL 6144
#define ST_BH 12288
#define ST_BL 16640
#define ST_SZ 20992
#define NSTG 4
#define PROJ_SMEM (NSTG * ST_SZ)

__global__ void __launch_bounds__(256, 2) proj_pipe()
{
    extern __shared__ char smc[];
    const uint32_t sb = smem_u32(smc);

    const int tid  = threadIdx.x;
    const int wid  = tid >> 5;
    const int lane = tid & 31;
    const int wm   = wid & 3;
    const int wn   = wid >> 2;

    const int p  = blockIdx.z;
    const int m0 = blockIdx.y * 128;
    const int n0 = blockIdx.x * 128;

    const __nv_bfloat16* Xh_ = g_Xh + (size_t)p * (MROWS * DDIM);
    const __nv_bfloat16* Xl_ = g_Xl + (size_t)p * (MROWS * DDIM);
    const __nv_bfloat16* Wh_ = g_Wh + (size_t)p * (DDIM * DDIM);
    const __nv_bfloat16* Wl_ = g_Wl + (size_t)p * (DDIM * DDIM);
    __nv_bfloat16* Ch = (p == 0) ? g_Qh : (p == 1) ? g_Kh : g_Vh;
    __nv_bfloat16* Cl = (p == 0) ? g_Ql : (p == 1) ? g_Kl : g_Vl;

    const int ar = tid >> 1, ac = tid & 1;
    const int br = tid >> 4, bc = tid & 15;
    const size_t ga0 = (size_t)(m0 + ar) * 512 + ac * 8;
    const size_t gb0 = (size_t)br * 512 + n0 + bc * 8;
    const uint32_t da = ar * 48 + ac * 16;
    const uint32_t db = br * 272 + bc * 16;

    const uint32_t a_lane = (uint32_t)(((wm * 32 + (lane & 15)) * 24 + (lane >> 4) * 8) * 2);
    const uint32_t b_lane = (uint32_t)(((lane & 15) * 136 + wn * 64 + (lane >> 4) * 8) * 2);

    float acc[2][8][4];
#pragma unroll
    for (int i = 0; i < 2; i++)
#pragma unroll
        for (int j = 0; j < 8; j++)
#pragma unroll
            for (int q = 0; q < 4; q++) acc[i][j][q] = 0.f;

#pragma unroll
    for (int s = 0; s < 3; s++) {
        const uint32_t st = sb + s * ST_SZ;
        const size_t ka = (size_t)s * 16;
        CP16(st + ST_AH + da, Xh_ + ga0 + ka);
        CP16(st + ST_AL + da, Xl_ + ga0 + ka);
        CP16(st + ST_BH + db, Wh_ + gb0 + ka * 512);
        CP16(st + ST_BL + db, Wl_ + gb0 + ka * 512);
        CP_COMMIT();
    }

    for (int c = 0; c < 32; c++) {
        CP_WAIT2();
        __syncthreads();

        if (c + 3 < 32) {
            const uint32_t st = sb + ((c + 3) & 3) * ST_SZ;
            const size_t ka = (size_t)(c + 3) * 16;
            CP16(st + ST_AH + da, Xh_ + ga0 + ka);
            CP16(st + ST_AL + da, Xl_ + ga0 + ka);
            CP16(st + ST_BH + db, Wh_ + gb0 + ka * 512);
            CP16(st + ST_BL + db, Wl_ + gb0 + ka * 512);
        }
        CP_COMMIT();

        const uint32_t stc = sb + (c & 3) * ST_SZ;
        uint32_t ah[2][4], al[2][4];
#pragma unroll
        for (int mt = 0; mt < 2; mt++) {
            const uint32_t ao = stc + a_lane + mt * 768;
            ldsm_x4(ah[mt], ao + ST_AH);
            ldsm_x4(al[mt], ao + ST_AL);
        }
#pragma unroll
        for (int np = 0; np < 4; np++) {
            uint32_t bh[4], bl[4];
            const uint32_t bo = stc + b_lane + np * 32;
            ldsm_x4_t(bh, bo + ST_BH);
            ldsm_x4_t(bl, bo + ST_BL);
#pragma unroll
            for (int mt = 0; mt < 2; mt++) {
#pragma unroll
                for (int nt = 0; nt < 2; nt++) {
                    float* d = acc[mt][np * 2 + nt];
                    mma_bf16(d, ah[mt], bh + nt * 2);
                    mma_bf16(d, al[mt], bh + nt * 2);
                    mma_bf16(d, ah[mt], bl + nt * 2);
                }
            }
        }
    }

    const int g = lane >> 2;
    const int t = lane & 3;
#pragma unroll
    for (int mt = 0; mt < 2; mt++) {
#pragma unroll
        for (int np = 0; np < 4; np++) {
#pragma unroll
            for (int nt = 0; nt < 2; nt++) {
                const float* d = acc[mt][np * 2 + nt];
                int row = m0 + wm * 32 + mt * 16 + g;
                int col = n0 + wn * 64 + np * 16 + nt * 8 + t * 2;
                uint16_t h0, l0, h1, l1;
                split_bf16(d[0], h0, l0);
                split_bf16(d[1], h1, l1);
                *(uint32_t*)(Ch + (size_t)row * 512 + col) = (uint32_t)h0 | ((uint32_t)h1 << 16);
                *(uint32_t*)(Cl + (size_t)row * 512 + col) = (uint32_t)l0 | ((uint32_t)l1 << 16);
                split_bf16(d[2], h0, l0);
                split_bf16(d[3], h1, l1);
                *(uint32_t*)(Ch + (size_t)(row + 8) * 512 + col) = (uint32_t)h0 | ((uint32_t)h1 << 16);
                *(uint32_t*)(Cl + (size_t)(row + 8) * 512 + col) = (uint32_t)l0 | ((uint32_t)l1 << 16);
            }
        }
    }
}

// ---------------------------------------------------------------------------
// Flash attention, no-max (scores provably small; softmax shift-invariant).
// 1 CTA (256 thr, 8 warps) per (bth, 128-row l-chunk).  K/V traffic halved
// vs 64-row CTAs: one K/V tile feeds 8 warps.
// smem: QH 18432 | QL 18432 | 2 stages x {KH,KL,VH,VL} each 9216 = 110592 B
// ---------------------------------------------------------------------------
#define AQH 0
#define AQL 18432
#define AST 36864
#define STG 36864
#define ATT_SMEM 110592

__global__ void __launch_bounds__(256, 1) attn_flash(
    const float* __restrict__ mask,
    const float* __restrict__ tau,
    const float* __restrict__ delta)
{
    extern __shared__ char smc[];
    const uint32_t sb = smem_u32(smc);

    const int tid  = threadIdx.x;
    const int wid  = tid >> 5;     // 0..7
    const int lane = tid & 31;
    const int wm   = wid;          // 8 warps x 16 rows = 128 l-rows

    const int bth = blockIdx.x;
    const int bt  = bth >> 3;
    const int h   = bth & 7;
    const int l0  = blockIdx.y * 128;

    // fold scale (0.125) and log2(e) into tau/delta
    const float ts = tau[0] * 0.125f * 1.4426950408889634f;
    const float ds = delta[0] * 0.125f * 1.4426950408889634f;

    const size_t hb = (size_t)bt * 512 * 512 + h * 64;
    const __nv_bfloat16* Kh_ = g_Kh + hb;
    const __nv_bfloat16* Kl_ = g_Kl + hb;
    const __nv_bfloat16* Vh_ = g_Vh + hb;
    const __nv_bfloat16* Vl_ = g_Vl + hb;

    const int arow = lane & 15;
    const int acol = (lane >> 4) * 8;
    const int krow = (lane & 7) | ((lane & 16) >> 1);
    const int kcol = lane & 8;
    const int g    = lane >> 2;
    const int tc   = (lane & 3) * 2;

    // ---- stage 0 K/V (64 s-rows x 8 chunks x 4 arrays; 256 thr -> 2 iters)
    {
#pragma unroll
        for (int i = 0; i < 2; i++) {
            int q = tid + i * 256;
            int row = q >> 3, c16 = q & 7;
            size_t gs = (size_t)row * 512 + c16 * 8;
            uint32_t dr = sb + AST + row * 144 + c16 * 16;
            CP16(dr +     0, Kh_ + gs);
            CP16(dr +  9216, Kl_ + gs);
            CP16(dr + 18432, Vh_ + gs);
            CP16(dr + 27648, Vl_ + gs);
        }
        CP_COMMIT();
    }

    // ---- stage Q (128 rows x 8 chunks per array; 4 iters per array) ----
    {
        const __nv_bfloat16* Qh_ = g_Qh + hb + (size_t)l0 * 512;
        const __nv_bfloat16* Ql_ = g_Ql + hb + (size_t)l0 * 512;
#pragma unroll
        for (int i = 0; i < 8; i++) {
            int arr = i >> 2;
            int q = tid + (i & 3) * 256;
            int row = q >> 3, c16 = q & 7;
            size_t gs = (size_t)row * 512 + c16 * 8;
            const __nv_bfloat16* src = arr ? Ql_ : Qh_;
            *(uint4*)(smc + (arr ? AQL : AQH) + row * 144 + c16 * 16) =
                *(const uint4*)(src + gs);
        }
    }
    __syncthreads();

    uint32_t qfh[4][4], qfl[4][4];
#pragma unroll
    for (int kk = 0; kk < 4; kk++) {
        uint32_t qoff = (uint32_t)(((wm * 16 + arow) * 72 + acol + kk * 16) * 2);
        ldsm_x4(qfh[kk], sb + AQH + qoff);
        ldsm_x4(qfl[kk], sb + AQL + qoff);
    }

    float O[8][4];
#pragma unroll
    for (int j = 0; j < 8; j++)
#pragma unroll
        for (int q = 0; q < 4; q++) O[j][q] = 0.f;
    float l_g = 0.f, l_h = 0.f;

    const float* mrow0 = mask + (size_t)(l0 + wm * 16 + g) * 512;
    const float* mrow1 = mrow0 + 8 * 512;

    for (int sc = 0; sc < 8; sc++) {
        CP_WAIT0();
        __syncthreads();
        const uint32_t stoff = sb + AST + (sc & 1) * STG;

        if (sc < 7) {
            const int s_row0 = (sc + 1) * 64;
            const uint32_t nst = sb + AST + ((sc + 1) & 1) * STG;
#pragma unroll
            for (int i = 0; i < 2; i++) {
                int q = tid + i * 256;
                int row = q >> 3, c16 = q & 7;
                size_t gs = (size_t)(s_row0 + row) * 512 + c16 * 8;
                uint32_t dr = nst + row * 144 + c16 * 16;
                CP16(dr +     0, Kh_ + gs);
                CP16(dr +  9216, Kl_ + gs);
                CP16(dr + 18432, Vh_ + gs);
                CP16(dr + 27648, Vl_ + gs);
            }
            CP_COMMIT();
        }

        // ---- QK^T for this 64-col s-tile ----
        float s[8][4];
#pragma unroll
        for (int j = 0; j < 8; j++)
#pragma unroll
            for (int q = 0; q < 4; q++) s[j][q] = 0.f;

#pragma unroll
        for (int kk = 0; kk < 4; kk++) {
#pragma unroll
            for (int np = 0; np < 4; np++) {
                uint32_t bh[4], bl[4];
                uint32_t koff = (uint32_t)(((np * 16 + krow) * 72 + kcol + kk * 16) * 2);
                ldsm_x4(bh, stoff + 0 + koff);
                ldsm_x4(bl, stoff + 9216 + koff);
#pragma unroll
                for (int nt = 0; nt < 2; nt++) {
                    float* d = s[np * 2 + nt];
                    mma_bf16(d, qfh[kk], bh + nt * 2);
                    mma_bf16(d, qfl[kk], bh + nt * 2);
                    mma_bf16(d, qfh[kk], bl + nt * 2);
                }
            }
        }

        // ---- transform + mask + exp2 (no max subtraction) ----
        float sg = 0.f, sh = 0.f;
#pragma unroll
        for (int j = 0; j < 8; j++) {
            const int col = sc * 64 + j * 8 + tc;
            float2 mk0 = *(const float2*)&mrow0[col];
            float2 mk1 = *(const float2*)&mrow1[col];
            s[j][0] = exp2f((s[j][0] * ts + ds) * mk0.x);
            s[j][1] = exp2f((s[j][1] * ts + ds) * mk0.y);
            s[j][2] = exp2f((s[j][2] * ts + ds) * mk1.x);
            s[j][3] = exp2f((s[j][3] * ts + ds) * mk1.y);
            sg += s[j][0] + s[j][1];
            sh += s[j][2] + s[j][3];
        }
        l_g += sg;
        l_h += sh;

        // ---- P @ V ----
#pragma unroll
        for (int mkk = 0; mkk < 4; mkk++) {
            const float* p0 = s[2 * mkk];
            const float* p1 = s[2 * mkk + 1];
            uint32_t pah[4], pal[4];
            pah[0] = pk2(p0[0], p0[1]);
            pah[1] = pk2(p0[2], p0[3]);
            pah[2] = pk2(p1[0], p1[1]);
            pah[3] = pk2(p1[2], p1[3]);
            pal[0] = pk2(rlo(p0[0]), rlo(p0[1]));
            pal[1] = pk2(rlo(p0[2]), rlo(p0[3]));
            pal[2] = pk2(rlo(p1[0]), rlo(p1[1]));
            pal[3] = pk2(rlo(p1[2]), rlo(p1[3]));
#pragma unroll
            for (int vn = 0; vn < 4; vn++) {
                uint32_t vh[4], vl[4];
                uint32_t voff = (uint32_t)(((mkk * 16 + arow) * 72 + vn * 16 + acol) * 2);
                ldsm_x4_t(vh, stoff + 18432 + voff);
                ldsm_x4_t(vl, stoff + 27648 + voff);
#pragma unroll
                for (int nt = 0; nt < 2; nt++) {
                    float* d = O[vn * 2 + nt];
                    mma_bf16(d, pah, vh + nt * 2);
                    mma_bf16(d, pal, vh + nt * 2);
                    mma_bf16(d, pah, vl + nt * 2);
                }
            }
        }
    }

    // ---- finalize ----
    float lg = l_g;
    lg += __shfl_xor_sync(0xffffffffu, lg, 1);
    lg += __shfl_xor_sync(0xffffffffu, lg, 2);
    float lh = l_h;
    lh += __shfl_xor_sync(0xffffffffu, lh, 1);
    lh += __shfl_xor_sync(0xffffffffu, lh, 2);
    const float ig = 1.0f / lg;
    const float ih = 1.0f / lh;

    float* dst0 = g_A + ((size_t)bth * 512 + l0 + wm * 16 + g) * 64;
#pragma unroll
    for (int vn = 0; vn < 4; vn++) {
#pragma unroll
        for (int nt = 0; nt < 2; nt++) {
            const float* d = O[vn * 2 + nt];
            const int col = vn * 16 + nt * 8 + tc;
            *(float2*)(dst0 + col)          = make_float2(d[0] * ig, d[1] * ig);
            *(float2*)(dst0 + 8 * 64 + col) = make_float2(d[2] * ih, d[3] * ih);
        }
    }
}

// ---------------------------------------------------------------------------
// Head reduction
// ---------------------------------------------------------------------------
__global__ void __launch_bounds__(256) reduce_heads(
    const float* __restrict__ w_head, float* __restrict__ out)
{
    int idx = blockIdx.x * 256 + threadIdx.x;
    int bt   = idx >> 15;
    int rest = idx & 32767;
    float s = 0.f;
#pragma unroll
    for (int h = 0; h < 8; h++)
        s += w_head[h] * g_A[(((size_t)bt * 8 + h) << 15) + rest];
    out[idx] = s;
}

// ---------------------------------------------------------------------------
extern "C" void kernel_launch(void* const* d_in, const int* in_sizes, int n_in,
                              void* d_out, int out_size)
{
    const float* queries = (const float*)d_in[0];
    const float* keys    = (const float*)d_in[1];
    const float* values  = (const float*)d_in[2];
    const float* mask    = (const float*)d_in[3];
    const float* Wq      = (const float*)d_in[4];
    const float* Wk      = (const float*)d_in[5];
    const float* Wv      = (const float*)d_in[6];
    const float* w_head  = (const float*)d_in[7];
    const float* tau     = (const float*)d_in[8];
    const float* delta   = (const float*)d_in[9];
    float* out = (float*)d_out;
    (void)in_sizes; (void)n_in; (void)out_size;

    cudaFuncSetAttribute(proj_pipe,
                         cudaFuncAttributeMaxDynamicSharedMemorySize, PROJ_SMEM);
    cudaFuncSetAttribute(attn_flash,
                         cudaFuncAttributeMaxDynamicSharedMemorySize, ATT_SMEM);

    prep_x<<<dim3(4096, 1, 3), 256>>>(queries, keys, values);
    prep_w<<<dim3(128, 1, 3), 256>>>(Wq, Wk, Wv);

    proj_pipe<<<dim3(4, 128, 3), 256, PROJ_SMEM>>>();

    attn_flash<<<dim3(256, 4), 256, ATT_SMEM>>>(mask, tau, delta);

    reduce_heads<<<4096, 256>>>(w_head, out);
}

// round 11
// speedup vs baseline: 1.4441x; 1.0134x over previous
#include <cuda_runtime.h>
#include <cuda_bf16.h>
#include <stdint.h>
#include <math.h>

// Problem constants
#define BTN 32      // B*T
#define LLEN 512    // L
#define DDIM 512    // D
#define NH 8        // H
#define ED 64       // KD == VD
#define MROWS (BTN * LLEN)   // 16384

// Scratch (device globals; allocation-free rule)
__device__ __align__(16) __nv_bfloat16 g_Xh[3 * MROWS * DDIM];
__device__ __align__(16) __nv_bfloat16 g_Xl[3 * MROWS * DDIM];
__device__ __align__(16) __nv_bfloat16 g_Wh[3 * DDIM * DDIM];
__device__ __align__(16) __nv_bfloat16 g_Wl[3 * DDIM * DDIM];
__device__ __align__(16) __nv_bfloat16 g_Qh[MROWS * DDIM];
__device__ __align__(16) __nv_bfloat16 g_Ql[MROWS * DDIM];
__device__ __align__(16) __nv_bfloat16 g_Kh[MROWS * DDIM];
__device__ __align__(16) __nv_bfloat16 g_Kl[MROWS * DDIM];
__device__ __align__(16) __nv_bfloat16 g_Vh[MROWS * DDIM];
__device__ __align__(16) __nv_bfloat16 g_Vl[MROWS * DDIM];
__device__ float g_A[BTN * NH * LLEN * ED];

// ---------------------------------------------------------------------------
// helpers
// ---------------------------------------------------------------------------
__device__ __forceinline__ uint32_t smem_u32(const void* p) {
    uint32_t a;
    asm("{ .reg .u64 t; cvta.to.shared.u64 t, %1; cvt.u32.u64 %0, t; }"
        : "=r"(a) : "l"(p));
    return a;
}

__device__ __forceinline__ void mma_bf16(float* d, const uint32_t* a, const uint32_t* b) {
    asm volatile(
        "mma.sync.aligned.m16n8k16.row.col.f32.bf16.bf16.f32 "
        "{%0,%1,%2,%3}, {%4,%5,%6,%7}, {%8,%9}, {%0,%1,%2,%3};"
        : "+f"(d[0]), "+f"(d[1]), "+f"(d[2]), "+f"(d[3])
        : "r"(a[0]), "r"(a[1]), "r"(a[2]), "r"(a[3]), "r"(b[0]), "r"(b[1]));
}

__device__ __forceinline__ void ldsm_x4(uint32_t* r, uint32_t addr) {
    asm volatile("ldmatrix.sync.aligned.m8n8.x4.shared.b16 {%0,%1,%2,%3}, [%4];"
                 : "=r"(r[0]), "=r"(r[1]), "=r"(r[2]), "=r"(r[3]) : "r"(addr));
}
__device__ __forceinline__ void ldsm_x4_t(uint32_t* r, uint32_t addr) {
    asm volatile("ldmatrix.sync.aligned.m8n8.x4.trans.shared.b16 {%0,%1,%2,%3}, [%4];"
                 : "=r"(r[0]), "=r"(r[1]), "=r"(r[2]), "=r"(r[3]) : "r"(addr));
}

#define CP16(dst, src) \
    asm volatile("cp.async.cg.shared.global [%0], [%1], 16;" :: "r"(dst), "l"(src))
#define CP_COMMIT() asm volatile("cp.async.commit_group;" ::: "memory")
#define CP_WAIT0()  asm volatile("cp.async.wait_group 0;" ::: "memory")
#define CP_WAIT2()  asm volatile("cp.async.wait_group 2;" ::: "memory")

__device__ __forceinline__ void split_bf16(float x, uint16_t& h, uint16_t& l) {
    __nv_bfloat16 hb = __float2bfloat16(x);
    float hf = __bfloat162float(hb);
    __nv_bfloat16 lb = __float2bfloat16(x - hf);
    h = __bfloat16_as_ushort(hb);
    l = __bfloat16_as_ushort(lb);
}

__device__ __forceinline__ void pack8(const float* xs, uint4& hi, uint4& lo) {
    uint16_t hs[8], ls[8];
#pragma unroll
    for (int j = 0; j < 8; j++) split_bf16(xs[j], hs[j], ls[j]);
    hi.x = (uint32_t)hs[0] | ((uint32_t)hs[1] << 16);
    hi.y = (uint32_t)hs[2] | ((uint32_t)hs[3] << 16);
    hi.z = (uint32_t)hs[4] | ((uint32_t)hs[5] << 16);
    hi.w = (uint32_t)hs[6] | ((uint32_t)hs[7] << 16);
    lo.x = (uint32_t)ls[0] | ((uint32_t)ls[1] << 16);
    lo.y = (uint32_t)ls[2] | ((uint32_t)ls[3] << 16);
    lo.z = (uint32_t)ls[4] | ((uint32_t)ls[5] << 16);
    lo.w = (uint32_t)ls[6] | ((uint32_t)ls[7] << 16);
}

__device__ __forceinline__ uint32_t pk2(float a, float b) {
    uint32_t r;
    asm("cvt.rn.bf16x2.f32 %0, %1, %2;" : "=r"(r) : "f"(b), "f"(a));
    return r;
}
__device__ __forceinline__ float rlo(float x) {
    return x - __bfloat162float(__float2bfloat16(x));
}

// ---------------------------------------------------------------------------
// prep kernels: fp32 -> bf16 hi/lo
// ---------------------------------------------------------------------------
__global__ void __launch_bounds__(256) prep_x(
    const float* __restrict__ q, const float* __restrict__ k, const float* __restrict__ v)
{
    const float* src = (blockIdx.z == 0) ? q : (blockIdx.z == 1) ? k : v;
    size_t base = (size_t)blockIdx.z * (MROWS * DDIM);
    size_t i = (size_t)blockIdx.x * 256 + threadIdx.x;
    const float4* s4 = (const float4*)src + i * 2;
    float4 a = s4[0], b = s4[1];
    float xs[8] = {a.x, a.y, a.z, a.w, b.x, b.y, b.z, b.w};
    uint4 hi, lo;
    pack8(xs, hi, lo);
    *(uint4*)&g_Xh[base + i * 8] = hi;
    *(uint4*)&g_Xl[base + i * 8] = lo;
}

__global__ void __launch_bounds__(256) prep_w(
    const float* __restrict__ Wq, const float* __restrict__ Wk, const float* __restrict__ Wv)
{
    const float* src = (blockIdx.z == 0) ? Wq : (blockIdx.z == 1) ? Wk : Wv;
    size_t base = (size_t)blockIdx.z * (DDIM * DDIM);
    size_t i = (size_t)blockIdx.x * 256 + threadIdx.x;
    const float4* s4 = (const float4*)src + i * 2;
    float4 a = s4[0], b = s4[1];
    float xs[8] = {a.x, a.y, a.z, a.w, b.x, b.y, b.z, b.w};
    uint4 hi, lo;
    pack8(xs, hi, lo);
    *(uint4*)&g_Wh[base + i * 8] = hi;
    *(uint4*)&g_Wl[base + i * 8] = lo;
}

// ---------------------------------------------------------------------------
// proj_pipe: 4-stage cp.async bf16 GEMM, CTA 128x128, BK=16, 2 CTAs/SM.
// ---------------------------------------------------------------------------
#define ST_AH 0
#define ST_AL 6144
#define ST_BH 12288
#define ST_BL 16640
#define ST_SZ 20992
#define NSTG 4
#define PROJ_SMEM (NSTG * ST_SZ)

__global__ void __launch_bounds__(256, 2) proj_pipe()
{
    extern __shared__ char smc[];
    const uint32_t sb = smem_u32(smc);

    const int tid  = threadIdx.x;
    const int wid  = tid >> 5;
    const int lane = tid & 31;
    const int wm   = wid & 3;
    const int wn   = wid >> 2;

    const int p  = blockIdx.z;
    const int m0 = blockIdx.y * 128;
    const int n0 = blockIdx.x * 128;

    const __nv_bfloat16* Xh_ = g_Xh + (size_t)p * (MROWS * DDIM);
    const __nv_bfloat16* Xl_ = g_Xl + (size_t)p * (MROWS * DDIM);
    const __nv_bfloat16* Wh_ = g_Wh + (size_t)p * (DDIM * DDIM);
    const __nv_bfloat16* Wl_ = g_Wl + (size_t)p * (DDIM * DDIM);
    __nv_bfloat16* Ch = (p == 0) ? g_Qh : (p == 1) ? g_Kh : g_Vh;
    __nv_bfloat16* Cl = (p == 0) ? g_Ql : (p == 1) ? g_Kl : g_Vl;

    const int ar = tid >> 1, ac = tid & 1;
    const int br = tid >> 4, bc = tid & 15;
    const size_t ga0 = (size_t)(m0 + ar) * 512 + ac * 8;
    const size_t gb0 = (size_t)br * 512 + n0 + bc * 8;
    const uint32_t da = ar * 48 + ac * 16;
    const uint32_t db = br * 272 + bc * 16;

    const uint32_t a_lane = (uint32_t)(((wm * 32 + (lane & 15)) * 24 + (lane >> 4) * 8) * 2);
    const uint32_t b_lane = (uint32_t)(((lane & 15) * 136 + wn * 64 + (lane >> 4) * 8) * 2);

    float acc[2][8][4];
#pragma unroll
    for (int i = 0; i < 2; i++)
#pragma unroll
        for (int j = 0; j < 8; j++)
#pragma unroll
            for (int q = 0; q < 4; q++) acc[i][j][q] = 0.f;

#pragma unroll
    for (int s = 0; s < 3; s++) {
        const uint32_t st = sb + s * ST_SZ;
        const size_t ka = (size_t)s * 16;
        CP16(st + ST_AH + da, Xh_ + ga0 + ka);
        CP16(st + ST_AL + da, Xl_ + ga0 + ka);
        CP16(st + ST_BH + db, Wh_ + gb0 + ka * 512);
        CP16(st + ST_BL + db, Wl_ + gb0 + ka * 512);
        CP_COMMIT();
    }

    for (int c = 0; c < 32; c++) {
        CP_WAIT2();
        __syncthreads();

        if (c + 3 < 32) {
            const uint32_t st = sb + ((c + 3) & 3) * ST_SZ;
            const size_t ka = (size_t)(c + 3) * 16;
            CP16(st + ST_AH + da, Xh_ + ga0 + ka);
            CP16(st + ST_AL + da, Xl_ + ga0 + ka);
            CP16(st + ST_BH + db, Wh_ + gb0 + ka * 512);
            CP16(st + ST_BL + db, Wl_ + gb0 + ka * 512);
        }
        CP_COMMIT();

        const uint32_t stc = sb + (c & 3) * ST_SZ;
        uint32_t ah[2][4], al[2][4];
#pragma unroll
        for (int mt = 0; mt < 2; mt++) {
            const uint32_t ao = stc + a_lane + mt * 768;
            ldsm_x4(ah[mt], ao + ST_AH);
            ldsm_x4(al[mt], ao + ST_AL);
        }
#pragma unroll
        for (int np = 0; np < 4; np++) {
            uint32_t bh[4], bl[4];
            const uint32_t bo = stc + b_lane + np * 32;
            ldsm_x4_t(bh, bo + ST_BH);
            ldsm_x4_t(bl, bo + ST_BL);
#pragma unroll
            for (int mt = 0; mt < 2; mt++) {
#pragma unroll
                for (int nt = 0; nt < 2; nt++) {
                    float* d = acc[mt][np * 2 + nt];
                    mma_bf16(d, ah[mt], bh + nt * 2);
                    mma_bf16(d, al[mt], bh + nt * 2);
                    mma_bf16(d, ah[mt], bl + nt * 2);
                }
            }
        }
    }

    const int g = lane >> 2;
    const int t = lane & 3;
#pragma unroll
    for (int mt = 0; mt < 2; mt++) {
#pragma unroll
        for (int np = 0; np < 4; np++) {
#pragma unroll
            for (int nt = 0; nt < 2; nt++) {
                const float* d = acc[mt][np * 2 + nt];
                int row = m0 + wm * 32 + mt * 16 + g;
                int col = n0 + wn * 64 + np * 16 + nt * 8 + t * 2;
                uint16_t h0, l0, h1, l1;
                split_bf16(d[0], h0, l0);
                split_bf16(d[1], h1, l1);
                *(uint32_t*)(Ch + (size_t)row * 512 + col) = (uint32_t)h0 | ((uint32_t)h1 << 16);
                *(uint32_t*)(Cl + (size_t)row * 512 + col) = (uint32_t)l0 | ((uint32_t)l1 << 16);
                split_bf16(d[2], h0, l0);
                split_bf16(d[3], h1, l1);
                *(uint32_t*)(Ch + (size_t)(row + 8) * 512 + col) = (uint32_t)h0 | ((uint32_t)h1 << 16);
                *(uint32_t*)(Cl + (size_t)(row + 8) * 512 + col) = (uint32_t)l0 | ((uint32_t)l1 << 16);
            }
        }
    }
}

// ---------------------------------------------------------------------------
// Flash attention, no-max, SOFTWARE-PIPELINED: PV of tile sc-1 overlaps
// exp2 of tile sc (order-independent accumulation since no online max).
// 1 CTA (128 thr, 4 warps) per (bth, 64-row l-chunk).
// smem: QH 9216 | QL 9216 | K 2 stages x 18432 | V 3 stages x 18432 = 110592
// ---------------------------------------------------------------------------
#define AQH 0
#define AQL 9216
#define AK  18432
#define AV  55296
#define KVS 18432
#define ATT_SMEM 110592

__device__ __forceinline__ void issue_kv(
    uint32_t kst, uint32_t vst, int s_row0, int tid,
    const __nv_bfloat16* Kh_, const __nv_bfloat16* Kl_,
    const __nv_bfloat16* Vh_, const __nv_bfloat16* Vl_)
{
#pragma unroll
    for (int i = 0; i < 4; i++) {
        int q = tid + i * 128;
        int row = q >> 3, c16 = q & 7;
        size_t gs = (size_t)(s_row0 + row) * 512 + c16 * 8;
        uint32_t dk = kst + row * 144 + c16 * 16;
        uint32_t dv = vst + row * 144 + c16 * 16;
        CP16(dk,        Kh_ + gs);
        CP16(dk + 9216, Kl_ + gs);
        CP16(dv,        Vh_ + gs);
        CP16(dv + 9216, Vl_ + gs);
    }
}

__global__ void __launch_bounds__(128, 2) attn_flash(
    const float* __restrict__ mask,
    const float* __restrict__ tau,
    const float* __restrict__ delta)
{
    extern __shared__ char smc[];
    const uint32_t sb = smem_u32(smc);

    const int tid  = threadIdx.x;
    const int wid  = tid >> 5;
    const int lane = tid & 31;
    const int wm   = wid;            // 4 warps x 16 rows

    const int bth = blockIdx.x;
    const int bt  = bth >> 3;
    const int h   = bth & 7;
    const int l0  = blockIdx.y * 64;

    const float ts = tau[0] * 0.125f * 1.4426950408889634f;
    const float ds = delta[0] * 0.125f * 1.4426950408889634f;

    const size_t hb = (size_t)bt * 512 * 512 + h * 64;
    const __nv_bfloat16* Kh_ = g_Kh + hb;
    const __nv_bfloat16* Kl_ = g_Kl + hb;
    const __nv_bfloat16* Vh_ = g_Vh + hb;
    const __nv_bfloat16* Vl_ = g_Vl + hb;

    const int arow = lane & 15;
    const int acol = (lane >> 4) * 8;
    const int krow = (lane & 7) | ((lane & 16) >> 1);
    const int kcol = lane & 8;
    const int g    = lane >> 2;
    const int tc   = (lane & 3) * 2;

    // ---- issue tile 0 (K stage 0, V stage 0) ----
    issue_kv(sb + AK, sb + AV, 0, tid, Kh_, Kl_, Vh_, Vl_);
    CP_COMMIT();

    // ---- stage Q (bf16 hi/lo, pitch 72 halves) ----
    {
        const __nv_bfloat16* Qh_ = g_Qh + hb + (size_t)l0 * 512;
        const __nv_bfloat16* Ql_ = g_Ql + hb + (size_t)l0 * 512;
#pragma unroll
        for (int i = 0; i < 8; i++) {
            int arr = i >> 2;
            int q = tid + (i & 3) * 128;
            int row = q >> 3, c16 = q & 7;
            size_t gs = (size_t)row * 512 + c16 * 8;
            const __nv_bfloat16* src = arr ? Ql_ : Qh_;
            *(uint4*)(smc + (arr ? AQL : AQH) + row * 144 + c16 * 16) =
                *(const uint4*)(src + gs);
        }
    }
    __syncthreads();

    uint32_t qfh[4][4], qfl[4][4];
#pragma unroll
    for (int kk = 0; kk < 4; kk++) {
        uint32_t qoff = (uint32_t)(((wm * 16 + arow) * 72 + acol + kk * 16) * 2);
        ldsm_x4(qfh[kk], sb + AQH + qoff);
        ldsm_x4(qfl[kk], sb + AQL + qoff);
    }

    float O[8][4];
#pragma unroll
    for (int j = 0; j < 8; j++)
#pragma unroll
        for (int q = 0; q < 4; q++) O[j][q] = 0.f;
    float l_g = 0.f, l_h = 0.f;
    uint32_t pph[4][4], ppl[4][4];   // packed P of previous tile

    const float* mrow0 = mask + (size_t)(l0 + wm * 16 + g) * 512;
    const float* mrow1 = mrow0 + 8 * 512;

    for (int sc = 0; sc < 8; sc++) {
        CP_WAIT0();
        __syncthreads();
        const uint32_t kst = sb + AK + (sc & 1) * KVS;

        // depth-1 prefetch of tile sc+1
        if (sc < 7)
            issue_kv(sb + AK + ((sc + 1) & 1) * KVS,
                     sb + AV + ((sc + 1) % 3) * KVS,
                     (sc + 1) * 64, tid, Kh_, Kl_, Vh_, Vl_);
        CP_COMMIT();

        // ---- QK^T (tensor) ----
        float s[8][4];
#pragma unroll
        for (int j = 0; j < 8; j++)
#pragma unroll
            for (int q = 0; q < 4; q++) s[j][q] = 0.f;

#pragma unroll
        for (int kk = 0; kk < 4; kk++) {
#pragma unroll
            for (int np = 0; np < 4; np++) {
                uint32_t bh[4], bl[4];
                uint32_t koff = (uint32_t)(((np * 16 + krow) * 72 + kcol + kk * 16) * 2);
                ldsm_x4(bh, kst + koff);
                ldsm_x4(bl, kst + 9216 + koff);
#pragma unroll
                for (int nt = 0; nt < 2; nt++) {
                    float* d = s[np * 2 + nt];
                    mma_bf16(d, qfh[kk], bh + nt * 2);
                    mma_bf16(d, qfl[kk], bh + nt * 2);
                    mma_bf16(d, qfh[kk], bl + nt * 2);
                }
            }
        }

        // ---- interleaved: exp2(sc) on MUFU  +  PV(sc-1) on tensor ----
        const uint32_t vprev = sb + AV + ((sc + 2) % 3) * KVS;   // (sc-1) mod 3
        float sg = 0.f, sh = 0.f;
#pragma unroll
        for (int m = 0; m < 4; m++) {
            // exp chunk (rows 2m, 2m+1 of this tile's score fragments)
#pragma unroll
            for (int j = 2 * m; j < 2 * m + 2; j++) {
                const int col = sc * 64 + j * 8 + tc;
                float2 mk0 = *(const float2*)&mrow0[col];
                float2 mk1 = *(const float2*)&mrow1[col];
                s[j][0] = exp2f((s[j][0] * ts + ds) * mk0.x);
                s[j][1] = exp2f((s[j][1] * ts + ds) * mk0.y);
                s[j][2] = exp2f((s[j][2] * ts + ds) * mk1.x);
                s[j][3] = exp2f((s[j][3] * ts + ds) * mk1.y);
                sg += s[j][0] + s[j][1];
                sh += s[j][2] + s[j][3];
            }
            // PV block mkk=m of PREVIOUS tile (independent of the exps above)
            if (sc > 0) {
#pragma unroll
                for (int vn = 0; vn < 4; vn++) {
                    uint32_t vh[4], vl[4];
                    uint32_t voff = (uint32_t)(((m * 16 + arow) * 72 + vn * 16 + acol) * 2);
                    ldsm_x4_t(vh, vprev + voff);
                    ldsm_x4_t(vl, vprev + 9216 + voff);
#pragma unroll
                    for (int nt = 0; nt < 2; nt++) {
                        float* d = O[vn * 2 + nt];
                        mma_bf16(d, pph[m], vh + nt * 2);
                        mma_bf16(d, ppl[m], vh + nt * 2);
                        mma_bf16(d, pph[m], vl + nt * 2);
                    }
                }
            }
        }
        l_g += sg;
        l_h += sh;

        // ---- pack new P fragments (carried to next iteration) ----
#pragma unroll
        for (int m = 0; m < 4; m++) {
            const float* p0 = s[2 * m];
            const float* p1 = s[2 * m + 1];
            pph[m][0] = pk2(p0[0], p0[1]);
            pph[m][1] = pk2(p0[2], p0[3]);
            pph[m][2] = pk2(p1[0], p1[1]);
            pph[m][3] = pk2(p1[2], p1[3]);
            ppl[m][0] = pk2(rlo(p0[0]), rlo(p0[1]));
            ppl[m][1] = pk2(rlo(p0[2]), rlo(p0[3]));
            ppl[m][2] = pk2(rlo(p1[0]), rlo(p1[1]));
            ppl[m][3] = pk2(rlo(p1[2]), rlo(p1[3]));
        }
    }

    // ---- drain: PV of the last tile (V stage 7%3 = 1) ----
    {
        const uint32_t vlast = sb + AV + (7 % 3) * KVS;
#pragma unroll
        for (int m = 0; m < 4; m++) {
#pragma unroll
            for (int vn = 0; vn < 4; vn++) {
                uint32_t vh[4], vl[4];
                uint32_t voff = (uint32_t)(((m * 16 + arow) * 72 + vn * 16 + acol) * 2);
                ldsm_x4_t(vh, vlast + voff);
                ldsm_x4_t(vl, vlast + 9216 + voff);
#pragma unroll
                for (int nt = 0; nt < 2; nt++) {
                    float* d = O[vn * 2 + nt];
                    mma_bf16(d, pph[m], vh + nt * 2);
                    mma_bf16(d, ppl[m], vh + nt * 2);
                    mma_bf16(d, pph[m], vl + nt * 2);
                }
            }
        }
    }

    // ---- finalize ----
    float lg = l_g;
    lg += __shfl_xor_sync(0xffffffffu, lg, 1);
    lg += __shfl_xor_sync(0xffffffffu, lg, 2);
    float lh = l_h;
    lh += __shfl_xor_sync(0xffffffffu, lh, 1);
    lh += __shfl_xor_sync(0xffffffffu, lh, 2);
    const float ig = 1.0f / lg;
    const float ih = 1.0f / lh;

    float* dst0 = g_A + ((size_t)bth * 512 + l0 + wm * 16 + g) * 64;
#pragma unroll
    for (int vn = 0; vn < 4; vn++) {
#pragma unroll
        for (int nt = 0; nt < 2; nt++) {
            const float* d = O[vn * 2 + nt];
            const int col = vn * 16 + nt * 8 + tc;
            *(float2*)(dst0 + col)          = make_float2(d[0] * ig, d[1] * ig);
            *(float2*)(dst0 + 8 * 64 + col) = make_float2(d[2] * ih, d[3] * ih);
        }
    }
}

// ---------------------------------------------------------------------------
// Head reduction
// ---------------------------------------------------------------------------
__global__ void __launch_bounds__(256) reduce_heads(
    const float* __restrict__ w_head, float* __restrict__ out)
{
    int idx = blockIdx.x * 256 + threadIdx.x;
    int bt   = idx >> 15;
    int rest = idx & 32767;
    float s = 0.f;
#pragma unroll
    for (int h = 0; h < 8; h++)
        s += w_head[h] * g_A[(((size_t)bt * 8 + h) << 15) + rest];
    out[idx] = s;
}

// ---------------------------------------------------------------------------
extern "C" void kernel_launch(void* const* d_in, const int* in_sizes, int n_in,
                              void* d_out, int out_size)
{
    const float* queries = (const float*)d_in[0];
    const float* keys    = (const float*)d_in[1];
    const float* values  = (const float*)d_in[2];
    const float* mask    = (const float*)d_in[3];
    const float* Wq      = (const float*)d_in[4];
    const float* Wk      = (const float*)d_in[5];
    const float* Wv      = (const float*)d_in[6];
    const float* w_head  = (const float*)d_in[7];
    const float* tau     = (const float*)d_in[8];
    const float* delta   = (const float*)d_in[9];
    float* out = (float*)d_out;
    (void)in_sizes; (void)n_in; (void)out_size;

    cudaFuncSetAttribute(proj_pipe,
                         cudaFuncAttributeMaxDynamicSharedMemorySize, PROJ_SMEM);
    cudaFuncSetAttribute(attn_flash,
                         cudaFuncAttributeMaxDynamicSharedMemorySize, ATT_SMEM);

    prep_x<<<dim3(4096, 1, 3), 256>>>(queries, keys, values);
    prep_w<<<dim3(128, 1, 3), 256>>>(Wq, Wk, Wv);

    proj_pipe<<<dim3(4, 128, 3), 256, PROJ_SMEM>>>();

    attn_flash<<<dim3(256, 8), 128, ATT_SMEM>>>(mask, tau, delta);

    reduce_heads<<<4096, 256>>>(w_head, out);
}

// round 12
// speedup vs baseline: 1.4482x; 1.0028x over previous
#include <cuda_runtime.h>
#include <cuda_bf16.h>
#include <stdint.h>
#include <math.h>

// Problem constants
#define BTN 32      // B*T
#define LLEN 512    // L
#define DDIM 512    // D
#define NH 8        // H
#define ED 64       // KD == VD
#define MROWS (BTN * LLEN)   // 16384

// Scratch (device globals; allocation-free rule)
__device__ __align__(16) __nv_bfloat16 g_Xh[3 * MROWS * DDIM];
__device__ __align__(16) __nv_bfloat16 g_Xl[3 * MROWS * DDIM];
__device__ __align__(16) __nv_bfloat16 g_Wh[3 * DDIM * DDIM];
__device__ __align__(16) __nv_bfloat16 g_Wl[3 * DDIM * DDIM];
__device__ __align__(16) __nv_bfloat16 g_Qh[MROWS * DDIM];
__device__ __align__(16) __nv_bfloat16 g_Ql[MROWS * DDIM];
__device__ __align__(16) __nv_bfloat16 g_Kh[MROWS * DDIM];
__device__ __align__(16) __nv_bfloat16 g_Kl[MROWS * DDIM];
__device__ __align__(16) __nv_bfloat16 g_Vh[MROWS * DDIM];
__device__ __align__(16) __nv_bfloat16 g_Vl[MROWS * DDIM];
__device__ float g_A[BTN * NH * LLEN * ED];

// ---------------------------------------------------------------------------
// helpers
// ---------------------------------------------------------------------------
__device__ __forceinline__ uint32_t smem_u32(const void* p) {
    uint32_t a;
    asm("{ .reg .u64 t; cvta.to.shared.u64 t, %1; cvt.u32.u64 %0, t; }"
        : "=r"(a) : "l"(p));
    return a;
}

__device__ __forceinline__ void mma_bf16(float* d, const uint32_t* a, const uint32_t* b) {
    asm volatile(
        "mma.sync.aligned.m16n8k16.row.col.f32.bf16.bf16.f32 "
        "{%0,%1,%2,%3}, {%4,%5,%6,%7}, {%8,%9}, {%0,%1,%2,%3};"
        : "+f"(d[0]), "+f"(d[1]), "+f"(d[2]), "+f"(d[3])
        : "r"(a[0]), "r"(a[1]), "r"(a[2]), "r"(a[3]), "r"(b[0]), "r"(b[1]));
}

__device__ __forceinline__ void ldsm_x4(uint32_t* r, uint32_t addr) {
    asm volatile("ldmatrix.sync.aligned.m8n8.x4.shared.b16 {%0,%1,%2,%3}, [%4];"
                 : "=r"(r[0]), "=r"(r[1]), "=r"(r[2]), "=r"(r[3]) : "r"(addr));
}
__device__ __forceinline__ void ldsm_x4_t(uint32_t* r, uint32_t addr) {
    asm volatile("ldmatrix.sync.aligned.m8n8.x4.trans.shared.b16 {%0,%1,%2,%3}, [%4];"
                 : "=r"(r[0]), "=r"(r[1]), "=r"(r[2]), "=r"(r[3]) : "r"(addr));
}

#define CP16(dst, src) \
    asm volatile("cp.async.cg.shared.global [%0], [%1], 16;" :: "r"(dst), "l"(src))
#define CP_COMMIT() asm volatile("cp.async.commit_group;" ::: "memory")
#define CP_WAIT0()  asm volatile("cp.async.wait_group 0;" ::: "memory")

__device__ __forceinline__ void split_bf16(float x, uint16_t& h, uint16_t& l) {
    __nv_bfloat16 hb = __float2bfloat16(x);
    float hf = __bfloat162float(hb);
    __nv_bfloat16 lb = __float2bfloat16(x - hf);
    h = __bfloat16_as_ushort(hb);
    l = __bfloat16_as_ushort(lb);
}

__device__ __forceinline__ void pack8(const float* xs, uint4& hi, uint4& lo) {
    uint16_t hs[8], ls[8];
#pragma unroll
    for (int j = 0; j < 8; j++) split_bf16(xs[j], hs[j], ls[j]);
    hi.x = (uint32_t)hs[0] | ((uint32_t)hs[1] << 16);
    hi.y = (uint32_t)hs[2] | ((uint32_t)hs[3] << 16);
    hi.z = (uint32_t)hs[4] | ((uint32_t)hs[5] << 16);
    hi.w = (uint32_t)hs[6] | ((uint32_t)hs[7] << 16);
    lo.x = (uint32_t)ls[0] | ((uint32_t)ls[1] << 16);
    lo.y = (uint32_t)ls[2] | ((uint32_t)ls[3] << 16);
    lo.z = (uint32_t)ls[4] | ((uint32_t)ls[5] << 16);
    lo.w = (uint32_t)ls[6] | ((uint32_t)ls[7] << 16);
}

__device__ __forceinline__ uint32_t pk2(float a, float b) {
    uint32_t r;
    asm("cvt.rn.bf16x2.f32 %0, %1, %2;" : "=r"(r) : "f"(b), "f"(a));
    return r;
}
__device__ __forceinline__ float rlo(float x) {
    return x - __bfloat162float(__float2bfloat16(x));
}

// ---------------------------------------------------------------------------
// prep kernels: fp32 -> bf16 hi/lo
// ---------------------------------------------------------------------------
__global__ void __launch_bounds__(256) prep_x(
    const float* __restrict__ q, const float* __restrict__ k, const float* __restrict__ v)
{
    const float* src = (blockIdx.z == 0) ? q : (blockIdx.z == 1) ? k : v;
    size_t base = (size_t)blockIdx.z * (MROWS * DDIM);
    size_t i = (size_t)blockIdx.x * 256 + threadIdx.x;
    const float4* s4 = (const float4*)src + i * 2;
    float4 a = s4[0], b = s4[1];
    float xs[8] = {a.x, a.y, a.z, a.w, b.x, b.y, b.z, b.w};
    uint4 hi, lo;
    pack8(xs, hi, lo);
    *(uint4*)&g_Xh[base + i * 8] = hi;
    *(uint4*)&g_Xl[base + i * 8] = lo;
}

__global__ void __launch_bounds__(256) prep_w(
    const float* __restrict__ Wq, const float* __restrict__ Wk, const float* __restrict__ Wv)
{
    const float* src = (blockIdx.z == 0) ? Wq : (blockIdx.z == 1) ? Wk : Wv;
    size_t base = (size_t)blockIdx.z * (DDIM * DDIM);
    size_t i = (size_t)blockIdx.x * 256 + threadIdx.x;
    const float4* s4 = (const float4*)src + i * 2;
    float4 a = s4[0], b = s4[1];
    float xs[8] = {a.x, a.y, a.z, a.w, b.x, b.y, b.z, b.w};
    uint4 hi, lo;
    pack8(xs, hi, lo);
    *(uint4*)&g_Wh[base + i * 8] = hi;
    *(uint4*)&g_Wl[base + i * 8] = lo;
}

// ---------------------------------------------------------------------------
// proj_pipe: BK=32, 2-stage cp.async double buffer, one sync per chunk.
// CTA 128x128, 256 thr, 2 CTAs/SM.
// stage (bytes): AH 0 (128 rows x 40h), AL 10240, BH 20480 (32 x 136h), BL 29184
// ---------------------------------------------------------------------------
#define ST_AH 0
#define ST_AL 10240
#define ST_BH 20480
#define ST_BL 29184
#define ST_SZ 37888
#define PROJ_SMEM (2 * ST_SZ)

__global__ void __launch_bounds__(256, 2) proj_pipe()
{
    extern __shared__ char smc[];
    const uint32_t sb = smem_u32(smc);

    const int tid  = threadIdx.x;
    const int wid  = tid >> 5;
    const int lane = tid & 31;
    const int wm   = wid & 3;
    const int wn   = wid >> 2;

    const int p  = blockIdx.z;
    const int m0 = blockIdx.y * 128;
    const int n0 = blockIdx.x * 128;

    const __nv_bfloat16* Xh_ = g_Xh + (size_t)p * (MROWS * DDIM);
    const __nv_bfloat16* Xl_ = g_Xl + (size_t)p * (MROWS * DDIM);
    const __nv_bfloat16* Wh_ = g_Wh + (size_t)p * (DDIM * DDIM);
    const __nv_bfloat16* Wl_ = g_Wl + (size_t)p * (DDIM * DDIM);
    __nv_bfloat16* Ch = (p == 0) ? g_Qh : (p == 1) ? g_Kh : g_Vh;
    __nv_bfloat16* Cl = (p == 0) ? g_Ql : (p == 1) ? g_Kl : g_Vl;

    // staging maps (per-thread, 2 tasks per array)
    const int ar0 = tid >> 1,  ac0 = (tid & 1);        // A: idx = tid -> row=idx>>2? use idx loop
    (void)ar0; (void)ac0;

    const uint32_t a_lane = (uint32_t)(((wm * 32 + (lane & 15)) * 40 + (lane >> 4) * 8) * 2);
    const uint32_t b_lane = (uint32_t)(((lane & 15) * 136 + wn * 64 + (lane >> 4) * 8) * 2);

    float acc[2][8][4];
#pragma unroll
    for (int i = 0; i < 2; i++)
#pragma unroll
        for (int j = 0; j < 8; j++)
#pragma unroll
            for (int q = 0; q < 4; q++) acc[i][j][q] = 0.f;

    // stage issue helper (inlined twice)
#define ISSUE_STAGE(stageBuf, k0)                                              \
    do {                                                                       \
        const uint32_t st_ = sb + (stageBuf) * ST_SZ;                          \
        _Pragma("unroll")                                                      \
        for (int i_ = 0; i_ < 2; i_++) {                                       \
            int idx = tid + i_ * 256;                                          \
            int arow_ = idx >> 2, ac16_ = idx & 3;                             \
            size_t ga_ = (size_t)(m0 + arow_) * 512 + (k0) + ac16_ * 8;        \
            uint32_t da_ = st_ + arow_ * 80 + ac16_ * 16;                      \
            CP16(da_ + ST_AH, Xh_ + ga_);                                      \
            CP16(da_ + ST_AL, Xl_ + ga_);                                      \
            int brow_ = idx >> 4, bc16_ = idx & 15;                            \
            size_t gb_ = (size_t)((k0) + brow_) * 512 + n0 + bc16_ * 8;        \
            uint32_t db_ = st_ + brow_ * 272 + bc16_ * 16;                     \
            CP16(db_ + ST_BH, Wh_ + gb_);                                      \
            CP16(db_ + ST_BL, Wl_ + gb_);                                      \
        }                                                                      \
    } while (0)

    // prologue: stage 0
    ISSUE_STAGE(0, 0);
    CP_COMMIT();

    for (int c = 0; c < 16; c++) {
        CP_WAIT0();
        __syncthreads();

        // refill other buffer for chunk c+1 (freed by compute c-1, safe post-sync)
        if (c + 1 < 16) {
            ISSUE_STAGE((c + 1) & 1, (c + 1) * 32);
        }
        CP_COMMIT();

        const uint32_t stc = sb + (c & 1) * ST_SZ;
#pragma unroll
        for (int k16 = 0; k16 < 32; k16 += 16) {
            const uint32_t ka = (uint32_t)(k16 * 2);       // A col byte offset
            const uint32_t kb = (uint32_t)(k16 * 272);     // B row byte offset
            uint32_t ah[2][4], al[2][4];
#pragma unroll
            for (int mt = 0; mt < 2; mt++) {
                const uint32_t ao = stc + a_lane + mt * 1280 + ka;
                ldsm_x4(ah[mt], ao + ST_AH);
                ldsm_x4(al[mt], ao + ST_AL);
            }
#pragma unroll
            for (int np = 0; np < 4; np++) {
                uint32_t bh[4], bl[4];
                const uint32_t bo = stc + b_lane + kb + np * 32;
                ldsm_x4_t(bh, bo + ST_BH);
                ldsm_x4_t(bl, bo + ST_BL);
#pragma unroll
                for (int mt = 0; mt < 2; mt++) {
#pragma unroll
                    for (int nt = 0; nt < 2; nt++) {
                        float* d = acc[mt][np * 2 + nt];
                        mma_bf16(d, ah[mt], bh + nt * 2);
                        mma_bf16(d, al[mt], bh + nt * 2);
                        mma_bf16(d, ah[mt], bl + nt * 2);
                    }
                }
            }
        }
    }
#undef ISSUE_STAGE

    const int g = lane >> 2;
    const int t = lane & 3;
#pragma unroll
    for (int mt = 0; mt < 2; mt++) {
#pragma unroll
        for (int np = 0; np < 4; np++) {
#pragma unroll
            for (int nt = 0; nt < 2; nt++) {
                const float* d = acc[mt][np * 2 + nt];
                int row = m0 + wm * 32 + mt * 16 + g;
                int col = n0 + wn * 64 + np * 16 + nt * 8 + t * 2;
                uint16_t h0, l0, h1, l1;
                split_bf16(d[0], h0, l0);
                split_bf16(d[1], h1, l1);
                *(uint32_t*)(Ch + (size_t)row * 512 + col) = (uint32_t)h0 | ((uint32_t)h1 << 16);
                *(uint32_t*)(Cl + (size_t)row * 512 + col) = (uint32_t)l0 | ((uint32_t)l1 << 16);
                split_bf16(d[2], h0, l0);
                split_bf16(d[3], h1, l1);
                *(uint32_t*)(Ch + (size_t)(row + 8) * 512 + col) = (uint32_t)h0 | ((uint32_t)h1 << 16);
                *(uint32_t*)(Cl + (size_t)(row + 8) * 512 + col) = (uint32_t)l0 | ((uint32_t)l1 << 16);
            }
        }
    }
}

// ---------------------------------------------------------------------------
// Flash attention (R11, best known): no-max, software-pipelined PV overlap.
// 1 CTA (128 thr, 4 warps) per (bth, 64-row l-chunk).
// smem: QH 9216 | QL 9216 | K 2 stages x 18432 | V 3 stages x 18432 = 110592
// ---------------------------------------------------------------------------
#define AQH 0
#define AQL 9216
#define AK  18432
#define AV  55296
#define KVS 18432
#define ATT_SMEM 110592

__device__ __forceinline__ void issue_kv(
    uint32_t kst, uint32_t vst, int s_row0, int tid,
    const __nv_bfloat16* Kh_, const __nv_bfloat16* Kl_,
    const __nv_bfloat16* Vh_, const __nv_bfloat16* Vl_)
{
#pragma unroll
    for (int i = 0; i < 4; i++) {
        int q = tid + i * 128;
        int row = q >> 3, c16 = q & 7;
        size_t gs = (size_t)(s_row0 + row) * 512 + c16 * 8;
        uint32_t dk = kst + row * 144 + c16 * 16;
        uint32_t dv = vst + row * 144 + c16 * 16;
        CP16(dk,        Kh_ + gs);
        CP16(dk + 9216, Kl_ + gs);
        CP16(dv,        Vh_ + gs);
        CP16(dv + 9216, Vl_ + gs);
    }
}

__global__ void __launch_bounds__(128, 2) attn_flash(
    const float* __restrict__ mask,
    const float* __restrict__ tau,
    const float* __restrict__ delta)
{
    extern __shared__ char smc[];
    const uint32_t sb = smem_u32(smc);

    const int tid  = threadIdx.x;
    const int wid  = tid >> 5;
    const int lane = tid & 31;
    const int wm   = wid;

    const int bth = blockIdx.x;
    const int bt  = bth >> 3;
    const int h   = bth & 7;
    const int l0  = blockIdx.y * 64;

    const float ts = tau[0] * 0.125f * 1.4426950408889634f;
    const float ds = delta[0] * 0.125f * 1.4426950408889634f;

    const size_t hb = (size_t)bt * 512 * 512 + h * 64;
    const __nv_bfloat16* Kh_ = g_Kh + hb;
    const __nv_bfloat16* Kl_ = g_Kl + hb;
    const __nv_bfloat16* Vh_ = g_Vh + hb;
    const __nv_bfloat16* Vl_ = g_Vl + hb;

    const int arow = lane & 15;
    const int acol = (lane >> 4) * 8;
    const int krow = (lane & 7) | ((lane & 16) >> 1);
    const int kcol = lane & 8;
    const int g    = lane >> 2;
    const int tc   = (lane & 3) * 2;

    issue_kv(sb + AK, sb + AV, 0, tid, Kh_, Kl_, Vh_, Vl_);
    CP_COMMIT();

    {
        const __nv_bfloat16* Qh_ = g_Qh + hb + (size_t)l0 * 512;
        const __nv_bfloat16* Ql_ = g_Ql + hb + (size_t)l0 * 512;
#pragma unroll
        for (int i = 0; i < 8; i++) {
            int arr = i >> 2;
            int q = tid + (i & 3) * 128;
            int row = q >> 3, c16 = q & 7;
            size_t gs = (size_t)row * 512 + c16 * 8;
            const __nv_bfloat16* src = arr ? Ql_ : Qh_;
            *(uint4*)(smc + (arr ? AQL : AQH) + row * 144 + c16 * 16) =
                *(const uint4*)(src + gs);
        }
    }
    __syncthreads();

    uint32_t qfh[4][4], qfl[4][4];
#pragma unroll
    for (int kk = 0; kk < 4; kk++) {
        uint32_t qoff = (uint32_t)(((wm * 16 + arow) * 72 + acol + kk * 16) * 2);
        ldsm_x4(qfh[kk], sb + AQH + qoff);
        ldsm_x4(qfl[kk], sb + AQL + qoff);
    }

    float O[8][4];
#pragma unroll
    for (int j = 0; j < 8; j++)
#pragma unroll
        for (int q = 0; q < 4; q++) O[j][q] = 0.f;
    float l_g = 0.f, l_h = 0.f;
    uint32_t pph[4][4], ppl[4][4];

    const float* mrow0 = mask + (size_t)(l0 + wm * 16 + g) * 512;
    const float* mrow1 = mrow0 + 8 * 512;

    for (int sc = 0; sc < 8; sc++) {
        CP_WAIT0();
        __syncthreads();
        const uint32_t kst = sb + AK + (sc & 1) * KVS;

        if (sc < 7)
            issue_kv(sb + AK + ((sc + 1) & 1) * KVS,
                     sb + AV + ((sc + 1) % 3) * KVS,
                     (sc + 1) * 64, tid, Kh_, Kl_, Vh_, Vl_);
        CP_COMMIT();

        float s[8][4];
#pragma unroll
        for (int j = 0; j < 8; j++)
#pragma unroll
            for (int q = 0; q < 4; q++) s[j][q] = 0.f;

#pragma unroll
        for (int kk = 0; kk < 4; kk++) {
#pragma unroll
            for (int np = 0; np < 4; np++) {
                uint32_t bh[4], bl[4];
                uint32_t koff = (uint32_t)(((np * 16 + krow) * 72 + kcol + kk * 16) * 2);
                ldsm_x4(bh, kst + koff);
                ldsm_x4(bl, kst + 9216 + koff);
#pragma unroll
                for (int nt = 0; nt < 2; nt++) {
                    float* d = s[np * 2 + nt];
                    mma_bf16(d, qfh[kk], bh + nt * 2);
                    mma_bf16(d, qfl[kk], bh + nt * 2);
                    mma_bf16(d, qfh[kk], bl + nt * 2);
                }
            }
        }

        const uint32_t vprev = sb + AV + ((sc + 2) % 3) * KVS;
        float sg = 0.f, sh = 0.f;
#pragma unroll
        for (int m = 0; m < 4; m++) {
#pragma unroll
            for (int j = 2 * m; j < 2 * m + 2; j++) {
                const int col = sc * 64 + j * 8 + tc;
                float2 mk0 = *(const float2*)&mrow0[col];
                float2 mk1 = *(const float2*)&mrow1[col];
                s[j][0] = exp2f((s[j][0] * ts + ds) * mk0.x);
                s[j][1] = exp2f((s[j][1] * ts + ds) * mk0.y);
                s[j][2] = exp2f((s[j][2] * ts + ds) * mk1.x);
                s[j][3] = exp2f((s[j][3] * ts + ds) * mk1.y);
                sg += s[j][0] + s[j][1];
                sh += s[j][2] + s[j][3];
            }
            if (sc > 0) {
#pragma unroll
                for (int vn = 0; vn < 4; vn++) {
                    uint32_t vh[4], vl[4];
                    uint32_t voff = (uint32_t)(((m * 16 + arow) * 72 + vn * 16 + acol) * 2);
                    ldsm_x4_t(vh, vprev + voff);
                    ldsm_x4_t(vl, vprev + 9216 + voff);
#pragma unroll
                    for (int nt = 0; nt < 2; nt++) {
                        float* d = O[vn * 2 + nt];
                        mma_bf16(d, pph[m], vh + nt * 2);
                        mma_bf16(d, ppl[m], vh + nt * 2);
                        mma_bf16(d, pph[m], vl + nt * 2);
                    }
                }
            }
        }
        l_g += sg;
        l_h += sh;

#pragma unroll
        for (int m = 0; m < 4; m++) {
            const float* p0 = s[2 * m];
            const float* p1 = s[2 * m + 1];
            pph[m][0] = pk2(p0[0], p0[1]);
            pph[m][1] = pk2(p0[2], p0[3]);
            pph[m][2] = pk2(p1[0], p1[1]);
            pph[m][3] = pk2(p1[2], p1[3]);
            ppl[m][0] = pk2(rlo(p0[0]), rlo(p0[1]));
            ppl[m][1] = pk2(rlo(p0[2]), rlo(p0[3]));
            ppl[m][2] = pk2(rlo(p1[0]), rlo(p1[1]));
            ppl[m][3] = pk2(rlo(p1[2]), rlo(p1[3]));
        }
    }

    {
        const uint32_t vlast = sb + AV + (7 % 3) * KVS;
#pragma unroll
        for (int m = 0; m < 4; m++) {
#pragma unroll
            for (int vn = 0; vn < 4; vn++) {
                uint32_t vh[4], vl[4];
                uint32_t voff = (uint32_t)(((m * 16 + arow) * 72 + vn * 16 + acol) * 2);
                ldsm_x4_t(vh, vlast + voff);
                ldsm_x4_t(vl, vlast + 9216 + voff);
#pragma unroll
                for (int nt = 0; nt < 2; nt++) {
                    float* d = O[vn * 2 + nt];
                    mma_bf16(d, pph[m], vh + nt * 2);
                    mma_bf16(d, ppl[m], vh + nt * 2);
                    mma_bf16(d, pph[m], vl + nt * 2);
                }
            }
        }
    }

    float lg = l_g;
    lg += __shfl_xor_sync(0xffffffffu, lg, 1);
    lg += __shfl_xor_sync(0xffffffffu, lg, 2);
    float lh = l_h;
    lh += __shfl_xor_sync(0xffffffffu, lh, 1);
    lh += __shfl_xor_sync(0xffffffffu, lh, 2);
    const float ig = 1.0f / lg;
    const float ih = 1.0f / lh;

    float* dst0 = g_A + ((size_t)bth * 512 + l0 + wm * 16 + g) * 64;
#pragma unroll
    for (int vn = 0; vn < 4; vn++) {
#pragma unroll
        for (int nt = 0; nt < 2; nt++) {
            const float* d = O[vn * 2 + nt];
            const int col = vn * 16 + nt * 8 + tc;
            *(float2*)(dst0 + col)          = make_float2(d[0] * ig, d[1] * ig);
            *(float2*)(dst0 + 8 * 64 + col) = make_float2(d[2] * ih, d[3] * ih);
        }
    }
}

// ---------------------------------------------------------------------------
// Head reduction
// ---------------------------------------------------------------------------
__global__ void __launch_bounds__(256) reduce_heads(
    const float* __restrict__ w_head, float* __restrict__ out)
{
    int idx = blockIdx.x * 256 + threadIdx.x;
    int bt   = idx >> 15;
    int rest = idx & 32767;
    float s = 0.f;
#pragma unroll
    for (int h = 0; h < 8; h++)
        s += w_head[h] * g_A[(((size_t)bt * 8 + h) << 15) + rest];
    out[idx] = s;
}

// ---------------------------------------------------------------------------
extern "C" void kernel_launch(void* const* d_in, const int* in_sizes, int n_in,
                              void* d_out, int out_size)
{
    const float* queries = (const float*)d_in[0];
    const float* keys    = (const float*)d_in[1];
    const float* values  = (const float*)d_in[2];
    const float* mask    = (const float*)d_in[3];
    const float* Wq      = (const float*)d_in[4];
    const float* Wk      = (const float*)d_in[5];
    const float* Wv      = (const float*)d_in[6];
    const float* w_head  = (const float*)d_in[7];
    const float* tau     = (const float*)d_in[8];
    const float* delta   = (const float*)d_in[9];
    float* out = (float*)d_out;
    (void)in_sizes; (void)n_in; (void)out_size;

    cudaFuncSetAttribute(proj_pipe,
                         cudaFuncAttributeMaxDynamicSharedMemorySize, PROJ_SMEM);
    cudaFuncSetAttribute(attn_flash,
                         cudaFuncAttributeMaxDynamicSharedMemorySize, ATT_SMEM);

    prep_x<<<dim3(4096, 1, 3), 256>>>(queries, keys, values);
    prep_w<<<dim3(128, 1, 3), 256>>>(Wq, Wk, Wv);

    proj_pipe<<<dim3(4, 128, 3), 256, PROJ_SMEM>>>();

    attn_flash<<<dim3(256, 8), 128, ATT_SMEM>>>(mask, tau, delta);

    reduce_heads<<<4096, 256>>>(w_head, out);
}

// round 13
// speedup vs baseline: 1.5275x; 1.0548x over previous
#include <cuda_runtime.h>
#include <cuda_bf16.h>
#include <stdint.h>
#include <math.h>

// Problem constants
#define BTN 32      // B*T
#define LLEN 512    // L
#define DDIM 512    // D
#define NH 8        // H
#define ED 64       // KD == VD
#define MROWS (BTN * LLEN)   // 16384

// Scratch (device globals; allocation-free rule)
__device__ __align__(16) __nv_bfloat16 g_Xh[3 * MROWS * DDIM];
__device__ __align__(16) __nv_bfloat16 g_Xl[3 * MROWS * DDIM];
__device__ __align__(16) __nv_bfloat16 g_Wh[3 * DDIM * DDIM];
__device__ __align__(16) __nv_bfloat16 g_Wl[3 * DDIM * DDIM];
__device__ __align__(16) __nv_bfloat16 g_Qh[MROWS * DDIM];
__device__ __align__(16) __nv_bfloat16 g_Ql[MROWS * DDIM];
__device__ __align__(16) __nv_bfloat16 g_Kh[MROWS * DDIM];
__device__ __align__(16) __nv_bfloat16 g_Kl[MROWS * DDIM];
__device__ __align__(16) __nv_bfloat16 g_Vh[MROWS * DDIM];
__device__ __align__(16) __nv_bfloat16 g_Vl[MROWS * DDIM];
__device__ float g_A[BTN * NH * LLEN * ED];

// ---------------------------------------------------------------------------
// helpers
// ---------------------------------------------------------------------------
__device__ __forceinline__ uint32_t smem_u32(const void* p) {
    uint32_t a;
    asm("{ .reg .u64 t; cvta.to.shared.u64 t, %1; cvt.u32.u64 %0, t; }"
        : "=r"(a) : "l"(p));
    return a;
}

__device__ __forceinline__ void mma_bf16(float* d, const uint32_t* a, const uint32_t* b) {
    asm volatile(
        "mma.sync.aligned.m16n8k16.row.col.f32.bf16.bf16.f32 "
        "{%0,%1,%2,%3}, {%4,%5,%6,%7}, {%8,%9}, {%0,%1,%2,%3};"
        : "+f"(d[0]), "+f"(d[1]), "+f"(d[2]), "+f"(d[3])
        : "r"(a[0]), "r"(a[1]), "r"(a[2]), "r"(a[3]), "r"(b[0]), "r"(b[1]));
}

__device__ __forceinline__ void ldsm_x4(uint32_t* r, uint32_t addr) {
    asm volatile("ldmatrix.sync.aligned.m8n8.x4.shared.b16 {%0,%1,%2,%3}, [%4];"
                 : "=r"(r[0]), "=r"(r[1]), "=r"(r[2]), "=r"(r[3]) : "r"(addr));
}
__device__ __forceinline__ void ldsm_x4_t(uint32_t* r, uint32_t addr) {
    asm volatile("ldmatrix.sync.aligned.m8n8.x4.trans.shared.b16 {%0,%1,%2,%3}, [%4];"
                 : "=r"(r[0]), "=r"(r[1]), "=r"(r[2]), "=r"(r[3]) : "r"(addr));
}

#define CP16(dst, src) \
    asm volatile("cp.async.cg.shared.global [%0], [%1], 16;" :: "r"(dst), "l"(src))
#define CP_COMMIT() asm volatile("cp.async.commit_group;" ::: "memory")
#define CP_WAIT0()  asm volatile("cp.async.wait_group 0;" ::: "memory")

__device__ __forceinline__ void split_bf16(float x, uint16_t& h, uint16_t& l) {
    __nv_bfloat16 hb = __float2bfloat16(x);
    float hf = __bfloat162float(hb);
    __nv_bfloat16 lb = __float2bfloat16(x - hf);
    h = __bfloat16_as_ushort(hb);
    l = __bfloat16_as_ushort(lb);
}

__device__ __forceinline__ void pack8(const float* xs, uint4& hi, uint4& lo) {
    uint16_t hs[8], ls[8];
#pragma unroll
    for (int j = 0; j < 8; j++) split_bf16(xs[j], hs[j], ls[j]);
    hi.x = (uint32_t)hs[0] | ((uint32_t)hs[1] << 16);
    hi.y = (uint32_t)hs[2] | ((uint32_t)hs[3] << 16);
    hi.z = (uint32_t)hs[4] | ((uint32_t)hs[5] << 16);
    hi.w = (uint32_t)hs[6] | ((uint32_t)hs[7] << 16);
    lo.x = (uint32_t)ls[0] | ((uint32_t)ls[1] << 16);
    lo.y = (uint32_t)ls[2] | ((uint32_t)ls[3] << 16);
    lo.z = (uint32_t)ls[4] | ((uint32_t)ls[5] << 16);
    lo.w = (uint32_t)ls[6] | ((uint32_t)ls[7] << 16);
}

__device__ __forceinline__ uint32_t pk2(float a, float b) {
    uint32_t r;
    asm("cvt.rn.bf16x2.f32 %0, %1, %2;" : "=r"(r) : "f"(b), "f"(a));
    return r;
}
__device__ __forceinline__ float rlo(float x) {
    return x - __bfloat162float(__float2bfloat16(x));
}

// ---------------------------------------------------------------------------
// prep kernels: fp32 -> bf16 hi/lo
// ---------------------------------------------------------------------------
__global__ void __launch_bounds__(256) prep_x(
    const float* __restrict__ q, const float* __restrict__ k, const float* __restrict__ v)
{
    const float* src = (blockIdx.z == 0) ? q : (blockIdx.z == 1) ? k : v;
    size_t base = (size_t)blockIdx.z * (MROWS * DDIM);
    size_t i = (size_t)blockIdx.x * 256 + threadIdx.x;
    const float4* s4 = (const float4*)src + i * 2;
    float4 a = s4[0], b = s4[1];
    float xs[8] = {a.x, a.y, a.z, a.w, b.x, b.y, b.z, b.w};
    uint4 hi, lo;
    pack8(xs, hi, lo);
    *(uint4*)&g_Xh[base + i * 8] = hi;
    *(uint4*)&g_Xl[base + i * 8] = lo;
}

__global__ void __launch_bounds__(256) prep_w(
    const float* __restrict__ Wq, const float* __restrict__ Wk, const float* __restrict__ Wv)
{
    const float* src = (blockIdx.z == 0) ? Wq : (blockIdx.z == 1) ? Wk : Wv;
    size_t base = (size_t)blockIdx.z * (DDIM * DDIM);
    size_t i = (size_t)blockIdx.x * 256 + threadIdx.x;
    const float4* s4 = (const float4*)src + i * 2;
    float4 a = s4[0], b = s4[1];
    float xs[8] = {a.x, a.y, a.z, a.w, b.x, b.y, b.z, b.w};
    uint4 hi, lo;
    pack8(xs, hi, lo);
    *(uint4*)&g_Wh[base + i * 8] = hi;
    *(uint4*)&g_Wl[base + i * 8] = lo;
}

// ---------------------------------------------------------------------------
// proj_pipe: BK=32, 2-stage cp.async double buffer (R12, passing)
// ---------------------------------------------------------------------------
#define ST_AH 0
#define ST_AL 10240
#define ST_BH 20480
#define ST_BL 29184
#define ST_SZ 37888
#define PROJ_SMEM (2 * ST_SZ)

__global__ void __launch_bounds__(256, 2) proj_pipe()
{
    extern __shared__ char smc[];
    const uint32_t sb = smem_u32(smc);

    const int tid  = threadIdx.x;
    const int wid  = tid >> 5;
    const int lane = tid & 31;
    const int wm   = wid & 3;
    const int wn   = wid >> 2;

    const int p  = blockIdx.z;
    const int m0 = blockIdx.y * 128;
    const int n0 = blockIdx.x * 128;

    const __nv_bfloat16* Xh_ = g_Xh + (size_t)p * (MROWS * DDIM);
    const __nv_bfloat16* Xl_ = g_Xl + (size_t)p * (MROWS * DDIM);
    const __nv_bfloat16* Wh_ = g_Wh + (size_t)p * (DDIM * DDIM);
    const __nv_bfloat16* Wl_ = g_Wl + (size_t)p * (DDIM * DDIM);
    __nv_bfloat16* Ch = (p == 0) ? g_Qh : (p == 1) ? g_Kh : g_Vh;
    __nv_bfloat16* Cl = (p == 0) ? g_Ql : (p == 1) ? g_Kl : g_Vl;

    const uint32_t a_lane = (uint32_t)(((wm * 32 + (lane & 15)) * 40 + (lane >> 4) * 8) * 2);
    const uint32_t b_lane = (uint32_t)(((lane & 15) * 136 + wn * 64 + (lane >> 4) * 8) * 2);

    float acc[2][8][4];
#pragma unroll
    for (int i = 0; i < 2; i++)
#pragma unroll
        for (int j = 0; j < 8; j++)
#pragma unroll
            for (int q = 0; q < 4; q++) acc[i][j][q] = 0.f;

#define ISSUE_STAGE(stageBuf, k0)                                              \
    do {                                                                       \
        const uint32_t st_ = sb + (stageBuf) * ST_SZ;                          \
        _Pragma("unroll")                                                      \
        for (int i_ = 0; i_ < 2; i_++) {                                       \
            int idx = tid + i_ * 256;                                          \
            int arow_ = idx >> 2, ac16_ = idx & 3;                             \
            size_t ga_ = (size_t)(m0 + arow_) * 512 + (k0) + ac16_ * 8;        \
            uint32_t da_ = st_ + arow_ * 80 + ac16_ * 16;                      \
            CP16(da_ + ST_AH, Xh_ + ga_);                                      \
            CP16(da_ + ST_AL, Xl_ + ga_);                                      \
            int brow_ = idx >> 4, bc16_ = idx & 15;                            \
            size_t gb_ = (size_t)((k0) + brow_) * 512 + n0 + bc16_ * 8;        \
            uint32_t db_ = st_ + brow_ * 272 + bc16_ * 16;                     \
            CP16(db_ + ST_BH, Wh_ + gb_);                                      \
            CP16(db_ + ST_BL, Wl_ + gb_);                                      \
        }                                                                      \
    } while (0)

    ISSUE_STAGE(0, 0);
    CP_COMMIT();

    for (int c = 0; c < 16; c++) {
        CP_WAIT0();
        __syncthreads();

        if (c + 1 < 16) {
            ISSUE_STAGE((c + 1) & 1, (c + 1) * 32);
        }
        CP_COMMIT();

        const uint32_t stc = sb + (c & 1) * ST_SZ;
#pragma unroll
        for (int k16 = 0; k16 < 32; k16 += 16) {
            const uint32_t ka = (uint32_t)(k16 * 2);
            const uint32_t kb = (uint32_t)(k16 * 272);
            uint32_t ah[2][4], al[2][4];
#pragma unroll
            for (int mt = 0; mt < 2; mt++) {
                const uint32_t ao = stc + a_lane + mt * 1280 + ka;
                ldsm_x4(ah[mt], ao + ST_AH);
                ldsm_x4(al[mt], ao + ST_AL);
            }
#pragma unroll
            for (int np = 0; np < 4; np++) {
                uint32_t bh[4], bl[4];
                const uint32_t bo = stc + b_lane + kb + np * 32;
                ldsm_x4_t(bh, bo + ST_BH);
                ldsm_x4_t(bl, bo + ST_BL);
#pragma unroll
                for (int mt = 0; mt < 2; mt++) {
#pragma unroll
                    for (int nt = 0; nt < 2; nt++) {
                        float* d = acc[mt][np * 2 + nt];
                        mma_bf16(d, ah[mt], bh + nt * 2);
                        mma_bf16(d, al[mt], bh + nt * 2);
                        mma_bf16(d, ah[mt], bl + nt * 2);
                    }
                }
            }
        }
    }
#undef ISSUE_STAGE

    const int g = lane >> 2;
    const int t = lane & 3;
#pragma unroll
    for (int mt = 0; mt < 2; mt++) {
#pragma unroll
        for (int np = 0; np < 4; np++) {
#pragma unroll
            for (int nt = 0; nt < 2; nt++) {
                const float* d = acc[mt][np * 2 + nt];
                int row = m0 + wm * 32 + mt * 16 + g;
                int col = n0 + wn * 64 + np * 16 + nt * 8 + t * 2;
                uint16_t h0, l0, h1, l1;
                split_bf16(d[0], h0, l0);
                split_bf16(d[1], h1, l1);
                *(uint32_t*)(Ch + (size_t)row * 512 + col) = (uint32_t)h0 | ((uint32_t)h1 << 16);
                *(uint32_t*)(Cl + (size_t)row * 512 + col) = (uint32_t)l0 | ((uint32_t)l1 << 16);
                split_bf16(d[2], h0, l0);
                split_bf16(d[3], h1, l1);
                *(uint32_t*)(Ch + (size_t)(row + 8) * 512 + col) = (uint32_t)h0 | ((uint32_t)h1 << 16);
                *(uint32_t*)(Cl + (size_t)(row + 8) * 512 + col) = (uint32_t)l0 | ((uint32_t)l1 << 16);
            }
        }
    }
}

// ---------------------------------------------------------------------------
// Flash attention, no-max, 3 CTAs/SM via Q/K1 smem overlay.
// 1 CTA (128 thr, 4 warps) per (bth, 64-row l-chunk).
// smem layout (bytes), 73728 total:
//   [0,     18432)  Q staging (prologue only) -> K stage 1 (from sc=0 prefetch)
//   [18432, 36864)  K stage 0
//   [36864, 55296)  V stage 0
//   [55296, 73728)  V stage 1
// Safety of overlay: Q fragments are loaded to registers BEFORE the loop-top
// __syncthreads of sc=0; the K1 cp.async for tile 1 is issued only after it.
// ---------------------------------------------------------------------------
#define AK0  18432
#define AV0  36864
#define AV1  55296
#define ATT_SMEM 73728

__device__ __forceinline__ void issue_kv(
    uint32_t kst, uint32_t vst, int s_row0, int tid,
    const __nv_bfloat16* Kh_, const __nv_bfloat16* Kl_,
    const __nv_bfloat16* Vh_, const __nv_bfloat16* Vl_)
{
#pragma unroll
    for (int i = 0; i < 4; i++) {
        int q = tid + i * 128;
        int row = q >> 3, c16 = q & 7;
        size_t gs = (size_t)(s_row0 + row) * 512 + c16 * 8;
        uint32_t dk = kst + row * 144 + c16 * 16;
        uint32_t dv = vst + row * 144 + c16 * 16;
        CP16(dk,        Kh_ + gs);
        CP16(dk + 9216, Kl_ + gs);
        CP16(dv,        Vh_ + gs);
        CP16(dv + 9216, Vl_ + gs);
    }
}

__global__ void __launch_bounds__(128, 3) attn_flash(
    const float* __restrict__ mask,
    const float* __restrict__ tau,
    const float* __restrict__ delta)
{
    extern __shared__ char smc[];
    const uint32_t sb = smem_u32(smc);

    const int tid  = threadIdx.x;
    const int wid  = tid >> 5;
    const int lane = tid & 31;
    const int wm   = wid;

    const int bth = blockIdx.x;
    const int bt  = bth >> 3;
    const int h   = bth & 7;
    const int l0  = blockIdx.y * 64;

    const float ts = tau[0] * 0.125f * 1.4426950408889634f;
    const float ds = delta[0] * 0.125f * 1.4426950408889634f;

    const size_t hb = (size_t)bt * 512 * 512 + h * 64;
    const __nv_bfloat16* Kh_ = g_Kh + hb;
    const __nv_bfloat16* Kl_ = g_Kl + hb;
    const __nv_bfloat16* Vh_ = g_Vh + hb;
    const __nv_bfloat16* Vl_ = g_Vl + hb;

    const int arow = lane & 15;
    const int acol = (lane >> 4) * 8;
    const int krow = (lane & 7) | ((lane & 16) >> 1);
    const int kcol = lane & 8;
    const int g    = lane >> 2;
    const int tc   = (lane & 3) * 2;

    // ---- prologue: issue K0 + V0 ----
    issue_kv(sb + AK0, sb + AV0, 0, tid, Kh_, Kl_, Vh_, Vl_);
    CP_COMMIT();

    // ---- stage Q into region 0 (plain stores) ----
    {
        const __nv_bfloat16* Qh_ = g_Qh + hb + (size_t)l0 * 512;
        const __nv_bfloat16* Ql_ = g_Ql + hb + (size_t)l0 * 512;
#pragma unroll
        for (int i = 0; i < 8; i++) {
            int arr = i >> 2;
            int q = tid + (i & 3) * 128;
            int row = q >> 3, c16 = q & 7;
            size_t gs = (size_t)row * 512 + c16 * 8;
            const __nv_bfloat16* src = arr ? Ql_ : Qh_;
            *(uint4*)(smc + arr * 9216 + row * 144 + c16 * 16) =
                *(const uint4*)(src + gs);
        }
    }
    __syncthreads();

    // ---- Q fragments into registers (region 0 is reused for K1 afterwards) ----
    uint32_t qfh[4][4], qfl[4][4];
#pragma unroll
    for (int kk = 0; kk < 4; kk++) {
        uint32_t qoff = (uint32_t)(((wm * 16 + arow) * 72 + acol + kk * 16) * 2);
        ldsm_x4(qfh[kk], sb + qoff);
        ldsm_x4(qfl[kk], sb + 9216 + qoff);
    }

    float O[8][4];
#pragma unroll
    for (int j = 0; j < 8; j++)
#pragma unroll
        for (int q = 0; q < 4; q++) O[j][q] = 0.f;
    float l_g = 0.f, l_h = 0.f;

    const float* mrow0 = mask + (size_t)(l0 + wm * 16 + g) * 512;
    const float* mrow1 = mrow0 + 8 * 512;

    for (int sc = 0; sc < 8; sc++) {
        CP_WAIT0();
        __syncthreads();      // at sc=0 this also orders qf loads before K1 issue
        const uint32_t kst = sb + ((sc & 1) ? 0u : (uint32_t)AK0);
        const uint32_t vst = sb + ((sc & 1) ? (uint32_t)AV1 : (uint32_t)AV0);

        if (sc < 7) {
            issue_kv(sb + (((sc + 1) & 1) ? 0u : (uint32_t)AK0),
                     sb + (((sc + 1) & 1) ? (uint32_t)AV1 : (uint32_t)AV0),
                     (sc + 1) * 64, tid, Kh_, Kl_, Vh_, Vl_);
        }
        CP_COMMIT();

        // ---- QK^T ----
        float s[8][4];
#pragma unroll
        for (int j = 0; j < 8; j++)
#pragma unroll
            for (int q = 0; q < 4; q++) s[j][q] = 0.f;

#pragma unroll
        for (int kk = 0; kk < 4; kk++) {
#pragma unroll
            for (int np = 0; np < 4; np++) {
                uint32_t bh[4], bl[4];
                uint32_t koff = (uint32_t)(((np * 16 + krow) * 72 + kcol + kk * 16) * 2);
                ldsm_x4(bh, kst + koff);
                ldsm_x4(bl, kst + 9216 + koff);
#pragma unroll
                for (int nt = 0; nt < 2; nt++) {
                    float* d = s[np * 2 + nt];
                    mma_bf16(d, qfh[kk], bh + nt * 2);
                    mma_bf16(d, qfl[kk], bh + nt * 2);
                    mma_bf16(d, qfh[kk], bl + nt * 2);
                }
            }
        }

        // ---- transform + mask + exp2 (no max subtraction) ----
        float sg = 0.f, sh = 0.f;
#pragma unroll
        for (int j = 0; j < 8; j++) {
            const int col = sc * 64 + j * 8 + tc;
            float2 mk0 = *(const float2*)&mrow0[col];
            float2 mk1 = *(const float2*)&mrow1[col];
            s[j][0] = exp2f((s[j][0] * ts + ds) * mk0.x);
            s[j][1] = exp2f((s[j][1] * ts + ds) * mk0.y);
            s[j][2] = exp2f((s[j][2] * ts + ds) * mk1.x);
            s[j][3] = exp2f((s[j][3] * ts + ds) * mk1.y);
            sg += s[j][0] + s[j][1];
            sh += s[j][2] + s[j][3];
        }
        l_g += sg;
        l_h += sh;

        // ---- P @ V ----
#pragma unroll
        for (int mkk = 0; mkk < 4; mkk++) {
            const float* p0 = s[2 * mkk];
            const float* p1 = s[2 * mkk + 1];
            uint32_t pah[4], pal[4];
            pah[0] = pk2(p0[0], p0[1]);
            pah[1] = pk2(p0[2], p0[3]);
            pah[2] = pk2(p1[0], p1[1]);
            pah[3] = pk2(p1[2], p1[3]);
            pal[0] = pk2(rlo(p0[0]), rlo(p0[1]));
            pal[1] = pk2(rlo(p0[2]), rlo(p0[3]));
            pal[2] = pk2(rlo(p1[0]), rlo(p1[1]));
            pal[3] = pk2(rlo(p1[2]), rlo(p1[3]));
#pragma unroll
            for (int vn = 0; vn < 4; vn++) {
                uint32_t vh[4], vl[4];
                uint32_t voff = (uint32_t)(((mkk * 16 + arow) * 72 + vn * 16 + acol) * 2);
                ldsm_x4_t(vh, vst + voff);
                ldsm_x4_t(vl, vst + 9216 + voff);
#pragma unroll
                for (int nt = 0; nt < 2; nt++) {
                    float* d = O[vn * 2 + nt];
                    mma_bf16(d, pah, vh + nt * 2);
                    mma_bf16(d, pal, vh + nt * 2);
                    mma_bf16(d, pah, vl + nt * 2);
                }
            }
        }
    }

    // ---- finalize ----
    float lg = l_g;
    lg += __shfl_xor_sync(0xffffffffu, lg, 1);
    lg += __shfl_xor_sync(0xffffffffu, lg, 2);
    float lh = l_h;
    lh += __shfl_xor_sync(0xffffffffu, lh, 1);
    lh += __shfl_xor_sync(0xffffffffu, lh, 2);
    const float ig = 1.0f / lg;
    const float ih = 1.0f / lh;

    float* dst0 = g_A + ((size_t)bth * 512 + l0 + wm * 16 + g) * 64;
#pragma unroll
    for (int vn = 0; vn < 4; vn++) {
#pragma unroll
        for (int nt = 0; nt < 2; nt++) {
            const float* d = O[vn * 2 + nt];
            const int col = vn * 16 + nt * 8 + tc;
            *(float2*)(dst0 + col)          = make_float2(d[0] * ig, d[1] * ig);
            *(float2*)(dst0 + 8 * 64 + col) = make_float2(d[2] * ih, d[3] * ih);
        }
    }
}

// ---------------------------------------------------------------------------
// Head reduction
// ---------------------------------------------------------------------------
__global__ void __launch_bounds__(256) reduce_heads(
    const float* __restrict__ w_head, float* __restrict__ out)
{
    int idx = blockIdx.x * 256 + threadIdx.x;
    int bt   = idx >> 15;
    int rest = idx & 32767;
    float s = 0.f;
#pragma unroll
    for (int h = 0; h < 8; h++)
        s += w_head[h] * g_A[(((size_t)bt * 8 + h) << 15) + rest];
    out[idx] = s;
}

// ---------------------------------------------------------------------------
extern "C" void kernel_launch(void* const* d_in, const int* in_sizes, int n_in,
                              void* d_out, int out_size)
{
    const float* queries = (const float*)d_in[0];
    const float* keys    = (const float*)d_in[1];
    const float* values  = (const float*)d_in[2];
    const float* mask    = (const float*)d_in[3];
    const float* Wq      = (const float*)d_in[4];
    const float* Wk      = (const float*)d_in[5];
    const float* Wv      = (const float*)d_in[6];
    const float* w_head  = (const float*)d_in[7];
    const float* tau     = (const float*)d_in[8];
    const float* delta   = (const float*)d_in[9];
    float* out = (float*)d_out;
    (void)in_sizes; (void)n_in; (void)out_size;

    cudaFuncSetAttribute(proj_pipe,
                         cudaFuncAttributeMaxDynamicSharedMemorySize, PROJ_SMEM);
    cudaFuncSetAttribute(attn_flash,
                         cudaFuncAttributeMaxDynamicSharedMemorySize, ATT_SMEM);

    prep_x<<<dim3(4096, 1, 3), 256>>>(queries, keys, values);
    prep_w<<<dim3(128, 1, 3), 256>>>(Wq, Wk, Wv);

    proj_pipe<<<dim3(4, 128, 3), 256, PROJ_SMEM>>>();

    attn_flash<<<dim3(256, 8), 128, ATT_SMEM>>>(mask, tau, delta);

    reduce_heads<<<4096, 256>>>(w_head, out);
}

// round 14
// speedup vs baseline: 1.6238x; 1.0630x over previous
#include <cuda_runtime.h>
#include <cuda_bf16.h>
#include <cuda_fp16.h>
#include <stdint.h>
#include <math.h>

// Problem constants
#define BTN 32      // B*T
#define LLEN 512    // L
#define DDIM 512    // D
#define NH 8        // H
#define ED 64       // KD == VD
#define MROWS (BTN * LLEN)   // 16384

// Scratch (device globals; allocation-free rule)
__device__ __align__(16) __nv_bfloat16 g_Xh[3 * MROWS * DDIM];
__device__ __align__(16) __nv_bfloat16 g_Xl[3 * MROWS * DDIM];
__device__ __align__(16) __nv_bfloat16 g_Wh[3 * DDIM * DDIM];
__device__ __align__(16) __nv_bfloat16 g_Wl[3 * DDIM * DDIM];
__device__ __align__(16) __nv_bfloat16 g_Qh[MROWS * DDIM];
__device__ __align__(16) __nv_bfloat16 g_Ql[MROWS * DDIM];
__device__ __align__(16) __nv_bfloat16 g_Kh[MROWS * DDIM];
__device__ __align__(16) __nv_bfloat16 g_Kl[MROWS * DDIM];
__device__ __align__(16) __half        g_Vh[MROWS * DDIM];   // fp16 hi
__device__ __align__(16) __half        g_Vl[MROWS * DDIM];   // fp16 lo
__device__ float g_A[BTN * NH * LLEN * ED];

// ---------------------------------------------------------------------------
// helpers
// ---------------------------------------------------------------------------
__device__ __forceinline__ uint32_t smem_u32(const void* p) {
    uint32_t a;
    asm("{ .reg .u64 t; cvta.to.shared.u64 t, %1; cvt.u32.u64 %0, t; }"
        : "=r"(a) : "l"(p));
    return a;
}

__device__ __forceinline__ void mma_bf16(float* d, const uint32_t* a, const uint32_t* b) {
    asm volatile(
        "mma.sync.aligned.m16n8k16.row.col.f32.bf16.bf16.f32 "
        "{%0,%1,%2,%3}, {%4,%5,%6,%7}, {%8,%9}, {%0,%1,%2,%3};"
        : "+f"(d[0]), "+f"(d[1]), "+f"(d[2]), "+f"(d[3])
        : "r"(a[0]), "r"(a[1]), "r"(a[2]), "r"(a[3]), "r"(b[0]), "r"(b[1]));
}

__device__ __forceinline__ void mma_f16(float* d, const uint32_t* a, const uint32_t* b) {
    asm volatile(
        "mma.sync.aligned.m16n8k16.row.col.f32.f16.f16.f32 "
        "{%0,%1,%2,%3}, {%4,%5,%6,%7}, {%8,%9}, {%0,%1,%2,%3};"
        : "+f"(d[0]), "+f"(d[1]), "+f"(d[2]), "+f"(d[3])
        : "r"(a[0]), "r"(a[1]), "r"(a[2]), "r"(a[3]), "r"(b[0]), "r"(b[1]));
}

__device__ __forceinline__ void ldsm_x4(uint32_t* r, uint32_t addr) {
    asm volatile("ldmatrix.sync.aligned.m8n8.x4.shared.b16 {%0,%1,%2,%3}, [%4];"
                 : "=r"(r[0]), "=r"(r[1]), "=r"(r[2]), "=r"(r[3]) : "r"(addr));
}
__device__ __forceinline__ void ldsm_x4_t(uint32_t* r, uint32_t addr) {
    asm volatile("ldmatrix.sync.aligned.m8n8.x4.trans.shared.b16 {%0,%1,%2,%3}, [%4];"
                 : "=r"(r[0]), "=r"(r[1]), "=r"(r[2]), "=r"(r[3]) : "r"(addr));
}

#define CP16(dst, src) \
    asm volatile("cp.async.cg.shared.global [%0], [%1], 16;" :: "r"(dst), "l"(src))
#define CP_COMMIT() asm volatile("cp.async.commit_group;" ::: "memory")
#define CP_WAIT0()  asm volatile("cp.async.wait_group 0;" ::: "memory")

__device__ __forceinline__ void split_bf16(float x, uint16_t& h, uint16_t& l) {
    __nv_bfloat16 hb = __float2bfloat16(x);
    float hf = __bfloat162float(hb);
    __nv_bfloat16 lb = __float2bfloat16(x - hf);
    h = __bfloat16_as_ushort(hb);
    l = __bfloat16_as_ushort(lb);
}

__device__ __forceinline__ void split_f16(float x, uint16_t& h, uint16_t& l) {
    __half hb = __float2half(x);
    float hf = __half2float(hb);
    __half lb = __float2half(x - hf);
    h = __half_as_ushort(hb);
    l = __half_as_ushort(lb);
}

__device__ __forceinline__ void pack8(const float* xs, uint4& hi, uint4& lo) {
    uint16_t hs[8], ls[8];
#pragma unroll
    for (int j = 0; j < 8; j++) split_bf16(xs[j], hs[j], ls[j]);
    hi.x = (uint32_t)hs[0] | ((uint32_t)hs[1] << 16);
    hi.y = (uint32_t)hs[2] | ((uint32_t)hs[3] << 16);
    hi.z = (uint32_t)hs[4] | ((uint32_t)hs[5] << 16);
    hi.w = (uint32_t)hs[6] | ((uint32_t)hs[7] << 16);
    lo.x = (uint32_t)ls[0] | ((uint32_t)ls[1] << 16);
    lo.y = (uint32_t)ls[2] | ((uint32_t)ls[3] << 16);
    lo.z = (uint32_t)ls[4] | ((uint32_t)ls[5] << 16);
    lo.w = (uint32_t)ls[6] | ((uint32_t)ls[7] << 16);
}

// pack two fp32 -> f16x2 (a -> lower half, b -> upper half)
__device__ __forceinline__ uint32_t pk2h(float a, float b) {
    uint32_t r;
    asm("cvt.rn.f16x2.f32 %0, %1, %2;" : "=r"(r) : "f"(b), "f"(a));
    return r;
}

// ---------------------------------------------------------------------------
// prep kernels: fp32 -> bf16 hi/lo
// ---------------------------------------------------------------------------
__global__ void __launch_bounds__(256) prep_x(
    const float* __restrict__ q, const float* __restrict__ k, const float* __restrict__ v)
{
    const float* src = (blockIdx.z == 0) ? q : (blockIdx.z == 1) ? k : v;
    size_t base = (size_t)blockIdx.z * (MROWS * DDIM);
    size_t i = (size_t)blockIdx.x * 256 + threadIdx.x;
    const float4* s4 = (const float4*)src + i * 2;
    float4 a = s4[0], b = s4[1];
    float xs[8] = {a.x, a.y, a.z, a.w, b.x, b.y, b.z, b.w};
    uint4 hi, lo;
    pack8(xs, hi, lo);
    *(uint4*)&g_Xh[base + i * 8] = hi;
    *(uint4*)&g_Xl[base + i * 8] = lo;
}

__global__ void __launch_bounds__(256) prep_w(
    const float* __restrict__ Wq, const float* __restrict__ Wk, const float* __restrict__ Wv)
{
    const float* src = (blockIdx.z == 0) ? Wq : (blockIdx.z == 1) ? Wk : Wv;
    size_t base = (size_t)blockIdx.z * (DDIM * DDIM);
    size_t i = (size_t)blockIdx.x * 256 + threadIdx.x;
    const float4* s4 = (const float4*)src + i * 2;
    float4 a = s4[0], b = s4[1];
    float xs[8] = {a.x, a.y, a.z, a.w, b.x, b.y, b.z, b.w};
    uint4 hi, lo;
    pack8(xs, hi, lo);
    *(uint4*)&g_Wh[base + i * 8] = hi;
    *(uint4*)&g_Wl[base + i * 8] = lo;
}

// ---------------------------------------------------------------------------
// proj_pipe: BK=32, 2-stage cp.async double buffer (R12 core).
// Epilogue: p<2 -> bf16 hi/lo (Q,K); p==2 -> fp16 hi/lo (V).
// ---------------------------------------------------------------------------
#define ST_AH 0
#define ST_AL 10240
#define ST_BH 20480
#define ST_BL 29184
#define ST_SZ 37888
#define PROJ_SMEM (2 * ST_SZ)

__global__ void __launch_bounds__(256, 2) proj_pipe()
{
    extern __shared__ char smc[];
    const uint32_t sb = smem_u32(smc);

    const int tid  = threadIdx.x;
    const int wid  = tid >> 5;
    const int lane = tid & 31;
    const int wm   = wid & 3;
    const int wn   = wid >> 2;

    const int p  = blockIdx.z;
    const int m0 = blockIdx.y * 128;
    const int n0 = blockIdx.x * 128;

    const __nv_bfloat16* Xh_ = g_Xh + (size_t)p * (MROWS * DDIM);
    const __nv_bfloat16* Xl_ = g_Xl + (size_t)p * (MROWS * DDIM);
    const __nv_bfloat16* Wh_ = g_Wh + (size_t)p * (DDIM * DDIM);
    const __nv_bfloat16* Wl_ = g_Wl + (size_t)p * (DDIM * DDIM);
    uint16_t* Ch = (p == 0) ? (uint16_t*)g_Qh : (p == 1) ? (uint16_t*)g_Kh : (uint16_t*)g_Vh;
    uint16_t* Cl = (p == 0) ? (uint16_t*)g_Ql : (p == 1) ? (uint16_t*)g_Kl : (uint16_t*)g_Vl;

    const uint32_t a_lane = (uint32_t)(((wm * 32 + (lane & 15)) * 40 + (lane >> 4) * 8) * 2);
    const uint32_t b_lane = (uint32_t)(((lane & 15) * 136 + wn * 64 + (lane >> 4) * 8) * 2);

    float acc[2][8][4];
#pragma unroll
    for (int i = 0; i < 2; i++)
#pragma unroll
        for (int j = 0; j < 8; j++)
#pragma unroll
            for (int q = 0; q < 4; q++) acc[i][j][q] = 0.f;

#define ISSUE_STAGE(stageBuf, k0)                                              \
    do {                                                                       \
        const uint32_t st_ = sb + (stageBuf) * ST_SZ;                          \
        _Pragma("unroll")                                                      \
        for (int i_ = 0; i_ < 2; i_++) {                                       \
            int idx = tid + i_ * 256;                                          \
            int arow_ = idx >> 2, ac16_ = idx & 3;                             \
            size_t ga_ = (size_t)(m0 + arow_) * 512 + (k0) + ac16_ * 8;        \
            uint32_t da_ = st_ + arow_ * 80 + ac16_ * 16;                      \
            CP16(da_ + ST_AH, Xh_ + ga_);                                      \
            CP16(da_ + ST_AL, Xl_ + ga_);                                      \
            int brow_ = idx >> 4, bc16_ = idx & 15;                            \
            size_t gb_ = (size_t)((k0) + brow_) * 512 + n0 + bc16_ * 8;        \
            uint32_t db_ = st_ + brow_ * 272 + bc16_ * 16;                     \
            CP16(db_ + ST_BH, Wh_ + gb_);                                      \
            CP16(db_ + ST_BL, Wl_ + gb_);                                      \
        }                                                                      \
    } while (0)

    ISSUE_STAGE(0, 0);
    CP_COMMIT();

    for (int c = 0; c < 16; c++) {
        CP_WAIT0();
        __syncthreads();

        if (c + 1 < 16) {
            ISSUE_STAGE((c + 1) & 1, (c + 1) * 32);
        }
        CP_COMMIT();

        const uint32_t stc = sb + (c & 1) * ST_SZ;
#pragma unroll
        for (int k16 = 0; k16 < 32; k16 += 16) {
            const uint32_t ka = (uint32_t)(k16 * 2);
            const uint32_t kb = (uint32_t)(k16 * 272);
            uint32_t ah[2][4], al[2][4];
#pragma unroll
            for (int mt = 0; mt < 2; mt++) {
                const uint32_t ao = stc + a_lane + mt * 1280 + ka;
                ldsm_x4(ah[mt], ao + ST_AH);
                ldsm_x4(al[mt], ao + ST_AL);
            }
#pragma unroll
            for (int np = 0; np < 4; np++) {
                uint32_t bh[4], bl[4];
                const uint32_t bo = stc + b_lane + kb + np * 32;
                ldsm_x4_t(bh, bo + ST_BH);
                ldsm_x4_t(bl, bo + ST_BL);
#pragma unroll
                for (int mt = 0; mt < 2; mt++) {
#pragma unroll
                    for (int nt = 0; nt < 2; nt++) {
                        float* d = acc[mt][np * 2 + nt];
                        mma_bf16(d, ah[mt], bh + nt * 2);
                        mma_bf16(d, al[mt], bh + nt * 2);
                        mma_bf16(d, ah[mt], bl + nt * 2);
                    }
                }
            }
        }
    }
#undef ISSUE_STAGE

    const int g = lane >> 2;
    const int t = lane & 3;
    const bool isv = (p == 2);
#pragma unroll
    for (int mt = 0; mt < 2; mt++) {
#pragma unroll
        for (int np = 0; np < 4; np++) {
#pragma unroll
            for (int nt = 0; nt < 2; nt++) {
                const float* d = acc[mt][np * 2 + nt];
                int row = m0 + wm * 32 + mt * 16 + g;
                int col = n0 + wn * 64 + np * 16 + nt * 8 + t * 2;
                uint16_t h0, l0, h1, l1;
                if (isv) { split_f16(d[0], h0, l0);  split_f16(d[1], h1, l1); }
                else     { split_bf16(d[0], h0, l0); split_bf16(d[1], h1, l1); }
                *(uint32_t*)(Ch + (size_t)row * 512 + col) = (uint32_t)h0 | ((uint32_t)h1 << 16);
                *(uint32_t*)(Cl + (size_t)row * 512 + col) = (uint32_t)l0 | ((uint32_t)l1 << 16);
                if (isv) { split_f16(d[2], h0, l0);  split_f16(d[3], h1, l1); }
                else     { split_bf16(d[2], h0, l0); split_bf16(d[3], h1, l1); }
                *(uint32_t*)(Ch + (size_t)(row + 8) * 512 + col) = (uint32_t)h0 | ((uint32_t)h1 << 16);
                *(uint32_t*)(Cl + (size_t)(row + 8) * 512 + col) = (uint32_t)l0 | ((uint32_t)l1 << 16);
            }
        }
    }
}

// ---------------------------------------------------------------------------
// Flash attention, no-max, 3 CTAs/SM (Q/K1 smem overlay), fp16 P single-term
// + fp16 V hi/lo (PV = 2 mma terms instead of 3).
// 1 CTA (128 thr, 4 warps) per (bth, 64-row l-chunk).  smem 73728 B.
// ---------------------------------------------------------------------------
#define AK0  18432
#define AV0  36864
#define AV1  55296
#define ATT_SMEM 73728

__device__ __forceinline__ void issue_kv(
    uint32_t kst, uint32_t vst, int s_row0, int tid,
    const __nv_bfloat16* Kh_, const __nv_bfloat16* Kl_,
    const __half* Vh_, const __half* Vl_)
{
#pragma unroll
    for (int i = 0; i < 4; i++) {
        int q = tid + i * 128;
        int row = q >> 3, c16 = q & 7;
        size_t gs = (size_t)(s_row0 + row) * 512 + c16 * 8;
        uint32_t dk = kst + row * 144 + c16 * 16;
        uint32_t dv = vst + row * 144 + c16 * 16;
        CP16(dk,        Kh_ + gs);
        CP16(dk + 9216, Kl_ + gs);
        CP16(dv,        Vh_ + gs);
        CP16(dv + 9216, Vl_ + gs);
    }
}

__global__ void __launch_bounds__(128, 3) attn_flash(
    const float* __restrict__ mask,
    const float* __restrict__ tau,
    const float* __restrict__ delta)
{
    extern __shared__ char smc[];
    const uint32_t sb = smem_u32(smc);

    const int tid  = threadIdx.x;
    const int wid  = tid >> 5;
    const int lane = tid & 31;
    const int wm   = wid;

    const int bth = blockIdx.x;
    const int bt  = bth >> 3;
    const int h   = bth & 7;
    const int l0  = blockIdx.y * 64;

    const float ts = tau[0] * 0.125f * 1.4426950408889634f;
    const float ds = delta[0] * 0.125f * 1.4426950408889634f;

    const size_t hb = (size_t)bt * 512 * 512 + h * 64;
    const __nv_bfloat16* Kh_ = g_Kh + hb;
    const __nv_bfloat16* Kl_ = g_Kl + hb;
    const __half* Vh_ = g_Vh + hb;
    const __half* Vl_ = g_Vl + hb;

    const int arow = lane & 15;
    const int acol = (lane >> 4) * 8;
    const int krow = (lane & 7) | ((lane & 16) >> 1);
    const int kcol = lane & 8;
    const int g    = lane >> 2;
    const int tc   = (lane & 3) * 2;

    // prologue: issue K0 + V0
    issue_kv(sb + AK0, sb + AV0, 0, tid, Kh_, Kl_, Vh_, Vl_);
    CP_COMMIT();

    // stage Q into region 0
    {
        const __nv_bfloat16* Qh_ = g_Qh + hb + (size_t)l0 * 512;
        const __nv_bfloat16* Ql_ = g_Ql + hb + (size_t)l0 * 512;
#pragma unroll
        for (int i = 0; i < 8; i++) {
            int arr = i >> 2;
            int q = tid + (i & 3) * 128;
            int row = q >> 3, c16 = q & 7;
            size_t gs = (size_t)row * 512 + c16 * 8;
            const __nv_bfloat16* src = arr ? Ql_ : Qh_;
            *(uint4*)(smc + arr * 9216 + row * 144 + c16 * 16) =
                *(const uint4*)(src + gs);
        }
    }
    __syncthreads();

    // Q fragments into registers
    uint32_t qfh[4][4], qfl[4][4];
#pragma unroll
    for (int kk = 0; kk < 4; kk++) {
        uint32_t qoff = (uint32_t)(((wm * 16 + arow) * 72 + acol + kk * 16) * 2);
        ldsm_x4(qfh[kk], sb + qoff);
        ldsm_x4(qfl[kk], sb + 9216 + qoff);
    }

    float O[8][4];
#pragma unroll
    for (int j = 0; j < 8; j++)
#pragma unroll
        for (int q = 0; q < 4; q++) O[j][q] = 0.f;
    float l_g = 0.f, l_h = 0.f;

    const float* mrow0 = mask + (size_t)(l0 + wm * 16 + g) * 512;
    const float* mrow1 = mrow0 + 8 * 512;

    for (int sc = 0; sc < 8; sc++) {
        CP_WAIT0();
        __syncthreads();
        const uint32_t kst = sb + ((sc & 1) ? 0u : (uint32_t)AK0);
        const uint32_t vst = sb + ((sc & 1) ? (uint32_t)AV1 : (uint32_t)AV0);

        if (sc < 7) {
            issue_kv(sb + (((sc + 1) & 1) ? 0u : (uint32_t)AK0),
                     sb + (((sc + 1) & 1) ? (uint32_t)AV1 : (uint32_t)AV0),
                     (sc + 1) * 64, tid, Kh_, Kl_, Vh_, Vl_);
        }
        CP_COMMIT();

        // ---- QK^T (bf16 3-term, unchanged) ----
        float s[8][4];
#pragma unroll
        for (int j = 0; j < 8; j++)
#pragma unroll
            for (int q = 0; q < 4; q++) s[j][q] = 0.f;

#pragma unroll
        for (int kk = 0; kk < 4; kk++) {
#pragma unroll
            for (int np = 0; np < 4; np++) {
                uint32_t bh[4], bl[4];
                uint32_t koff = (uint32_t)(((np * 16 + krow) * 72 + kcol + kk * 16) * 2);
                ldsm_x4(bh, kst + koff);
                ldsm_x4(bl, kst + 9216 + koff);
#pragma unroll
                for (int nt = 0; nt < 2; nt++) {
                    float* d = s[np * 2 + nt];
                    mma_bf16(d, qfh[kk], bh + nt * 2);
                    mma_bf16(d, qfl[kk], bh + nt * 2);
                    mma_bf16(d, qfh[kk], bl + nt * 2);
                }
            }
        }

        // ---- transform + mask + exp2 ----
        float sg = 0.f, sh = 0.f;
#pragma unroll
        for (int j = 0; j < 8; j++) {
            const int col = sc * 64 + j * 8 + tc;
            float2 mk0 = *(const float2*)&mrow0[col];
            float2 mk1 = *(const float2*)&mrow1[col];
            s[j][0] = exp2f((s[j][0] * ts + ds) * mk0.x);
            s[j][1] = exp2f((s[j][1] * ts + ds) * mk0.y);
            s[j][2] = exp2f((s[j][2] * ts + ds) * mk1.x);
            s[j][3] = exp2f((s[j][3] * ts + ds) * mk1.y);
            sg += s[j][0] + s[j][1];
            sh += s[j][2] + s[j][3];
        }
        l_g += sg;
        l_h += sh;

        // ---- P @ V : single fp16 P x (Vh + Vl) = 2 terms ----
#pragma unroll
        for (int mkk = 0; mkk < 4; mkk++) {
            const float* p0 = s[2 * mkk];
            const float* p1 = s[2 * mkk + 1];
            uint32_t pah[4];
            pah[0] = pk2h(p0[0], p0[1]);
            pah[1] = pk2h(p0[2], p0[3]);
            pah[2] = pk2h(p1[0], p1[1]);
            pah[3] = pk2h(p1[2], p1[3]);
#pragma unroll
            for (int vn = 0; vn < 4; vn++) {
                uint32_t vh[4], vl[4];
                uint32_t voff = (uint32_t)(((mkk * 16 + arow) * 72 + vn * 16 + acol) * 2);
                ldsm_x4_t(vh, vst + voff);
                ldsm_x4_t(vl, vst + 9216 + voff);
#pragma unroll
                for (int nt = 0; nt < 2; nt++) {
                    float* d = O[vn * 2 + nt];
                    mma_f16(d, pah, vh + nt * 2);
                    mma_f16(d, pah, vl + nt * 2);
                }
            }
        }
    }

    // ---- finalize ----
    float lg = l_g;
    lg += __shfl_xor_sync(0xffffffffu, lg, 1);
    lg += __shfl_xor_sync(0xffffffffu, lg, 2);
    float lh = l_h;
    lh += __shfl_xor_sync(0xffffffffu, lh, 1);
    lh += __shfl_xor_sync(0xffffffffu, lh, 2);
    const float ig = 1.0f / lg;
    const float ih = 1.0f / lh;

    float* dst0 = g_A + ((size_t)bth * 512 + l0 + wm * 16 + g) * 64;
#pragma unroll
    for (int vn = 0; vn < 4; vn++) {
#pragma unroll
        for (int nt = 0; nt < 2; nt++) {
            const float* d = O[vn * 2 + nt];
            const int col = vn * 16 + nt * 8 + tc;
            *(float2*)(dst0 + col)          = make_float2(d[0] * ig, d[1] * ig);
            *(float2*)(dst0 + 8 * 64 + col) = make_float2(d[2] * ih, d[3] * ih);
        }
    }
}

// ---------------------------------------------------------------------------
// Head reduction
// ---------------------------------------------------------------------------
__global__ void __launch_bounds__(256) reduce_heads(
    const float* __restrict__ w_head, float* __restrict__ out)
{
    int idx = blockIdx.x * 256 + threadIdx.x;
    int bt   = idx >> 15;
    int rest = idx & 32767;
    float s = 0.f;
#pragma unroll
    for (int h = 0; h < 8; h++)
        s += w_head[h] * g_A[(((size_t)bt * 8 + h) << 15) + rest];
    out[idx] = s;
}

// ---------------------------------------------------------------------------
extern "C" void kernel_launch(void* const* d_in, const int* in_sizes, int n_in,
                              void* d_out, int out_size)
{
    const float* queries = (const float*)d_in[0];
    const float* keys    = (const float*)d_in[1];
    const float* values  = (const float*)d_in[2];
    const float* mask    = (const float*)d_in[3];
    const float* Wq      = (const float*)d_in[4];
    const float* Wk      = (const float*)d_in[5];
    const float* Wv      = (const float*)d_in[6];
    const float* w_head  = (const float*)d_in[7];
    const float* tau     = (const float*)d_in[8];
    const float* delta   = (const float*)d_in[9];
    float* out = (float*)d_out;
    (void)in_sizes; (void)n_in; (void)out_size;

    cudaFuncSetAttribute(proj_pipe,
                         cudaFuncAttributeMaxDynamicSharedMemorySize, PROJ_SMEM);
    cudaFuncSetAttribute(attn_flash,
                         cudaFuncAttributeMaxDynamicSharedMemorySize, ATT_SMEM);

    prep_x<<<dim3(4096, 1, 3), 256>>>(queries, keys, values);
    prep_w<<<dim3(128, 1, 3), 256>>>(Wq, Wk, Wv);

    proj_pipe<<<dim3(4, 128, 3), 256, PROJ_SMEM>>>();

    attn_flash<<<dim3(256, 8), 128, ATT_SMEM>>>(mask, tau, delta);

    reduce_heads<<<4096, 256>>>(w_head, out);
}